// round 1
// baseline (speedup 1.0000x reference)
#include <cuda_runtime.h>
#include <cuda_bf16.h>

#define FULLMASK 0xffffffffu

// Problem dims (static for this dataset)
//   B=4, B_dim=64 -> B_=256 windows; N=196; C=512; H=16; hd=32
static constexpr int NWIN   = 256;     // B_
static constexpr int NTOK   = 196;     // N
static constexpr int NHEAD  = 16;      // H
static constexpr int HD     = 32;      // head dim
static constexpr int CDIM   = 512;     // C
static constexpr int MROWS  = NWIN * NTOK;  // 50176

// Scratch (static device globals; no allocation at runtime)
__device__ float g_K[NWIN * NHEAD * NTOK * HD];     // [b_,h,n,d]
__device__ float g_V[NWIN * NHEAD * NTOK * HD];
__device__ float g_att[MROWS * CDIM];               // attention output, (B_,N,C)

// ---------------------------------------------------------------------------
// SGEMM 128x128x8, 256 threads, 8x8 microtile.  C[m,c] = sum_k A[m,k]*W[c,k]
// Epilogues differ: kv scatters into g_K/g_V layout; proj writes d_out.
// ---------------------------------------------------------------------------
__global__ __launch_bounds__(256, 2)
void kv_gemm_kernel(const float* __restrict__ A,     // x: (50176, 512)
                    const float* __restrict__ W,     // kv_w: (1024, 512)
                    const float* __restrict__ bias)  // kv_b: (1024)
{
    __shared__ float As[8][128];
    __shared__ float Bs[8][128];
    const int tid = threadIdx.x;
    const int m0 = blockIdx.y * 128;
    const int n0 = blockIdx.x * 128;
    const int lr = tid >> 1;            // 0..127 (row within tile)
    const int lc = (tid & 1) * 4;       // 0 or 4 (k offset of float4)
    const float* Ap = A + (size_t)(m0 + lr) * CDIM + lc;
    const float* Wp = W + (size_t)(n0 + lr) * CDIM + lc;
    const int tr = (tid >> 4) * 8;      // microtile row base
    const int tc = (tid & 15) * 8;      // microtile col base

    float acc[8][8];
    #pragma unroll
    for (int i = 0; i < 8; i++)
        #pragma unroll
        for (int j = 0; j < 8; j++) acc[i][j] = 0.f;

    for (int k0 = 0; k0 < CDIM; k0 += 8) {
        float4 av = *(const float4*)(Ap + k0);
        float4 wv = *(const float4*)(Wp + k0);
        As[lc + 0][lr] = av.x; As[lc + 1][lr] = av.y;
        As[lc + 2][lr] = av.z; As[lc + 3][lr] = av.w;
        Bs[lc + 0][lr] = wv.x; Bs[lc + 1][lr] = wv.y;
        Bs[lc + 2][lr] = wv.z; Bs[lc + 3][lr] = wv.w;
        __syncthreads();
        #pragma unroll
        for (int k = 0; k < 8; k++) {
            float ar[8], br[8];
            #pragma unroll
            for (int i = 0; i < 8; i++) ar[i] = As[k][tr + i];
            #pragma unroll
            for (int j = 0; j < 8; j++) br[j] = Bs[k][tc + j];
            #pragma unroll
            for (int i = 0; i < 8; i++)
                #pragma unroll
                for (int j = 0; j < 8; j++)
                    acc[i][j] = fmaf(ar[i], br[j], acc[i][j]);
        }
        __syncthreads();
    }

    // Scatter epilogue: c in [0,1024); which = c/512 (K or V), h=(c/32)%16, d=c%32
    #pragma unroll
    for (int i = 0; i < 8; i++) {
        int m  = m0 + tr + i;
        int b_ = m / NTOK;
        int n  = m - b_ * NTOK;
        #pragma unroll
        for (int j = 0; j < 8; j++) {
            int c = n0 + tc + j;
            float v = acc[i][j] + bias[c];
            float* dst = (c < CDIM) ? g_K : g_V;
            int cc = c & (CDIM - 1);
            int h = cc >> 5, d = cc & 31;
            dst[((((b_ << 4) + h) * NTOK) + n) * HD + d] = v;
        }
    }
}

__global__ __launch_bounds__(256, 2)
void proj_gemm_kernel(const float* __restrict__ W,     // proj_w: (512, 512)
                      const float* __restrict__ bias,  // proj_b
                      float* __restrict__ out)         // (50176, 512)
{
    __shared__ float As[8][128];
    __shared__ float Bs[8][128];
    const float* A = g_att;
    const int tid = threadIdx.x;
    const int m0 = blockIdx.y * 128;
    const int n0 = blockIdx.x * 128;
    const int lr = tid >> 1;
    const int lc = (tid & 1) * 4;
    const float* Ap = A + (size_t)(m0 + lr) * CDIM + lc;
    const float* Wp = W + (size_t)(n0 + lr) * CDIM + lc;
    const int tr = (tid >> 4) * 8;
    const int tc = (tid & 15) * 8;

    float acc[8][8];
    #pragma unroll
    for (int i = 0; i < 8; i++)
        #pragma unroll
        for (int j = 0; j < 8; j++) acc[i][j] = 0.f;

    for (int k0 = 0; k0 < CDIM; k0 += 8) {
        float4 av = *(const float4*)(Ap + k0);
        float4 wv = *(const float4*)(Wp + k0);
        As[lc + 0][lr] = av.x; As[lc + 1][lr] = av.y;
        As[lc + 2][lr] = av.z; As[lc + 3][lr] = av.w;
        Bs[lc + 0][lr] = wv.x; Bs[lc + 1][lr] = wv.y;
        Bs[lc + 2][lr] = wv.z; Bs[lc + 3][lr] = wv.w;
        __syncthreads();
        #pragma unroll
        for (int k = 0; k < 8; k++) {
            float ar[8], br[8];
            #pragma unroll
            for (int i = 0; i < 8; i++) ar[i] = As[k][tr + i];
            #pragma unroll
            for (int j = 0; j < 8; j++) br[j] = Bs[k][tc + j];
            #pragma unroll
            for (int i = 0; i < 8; i++)
                #pragma unroll
                for (int j = 0; j < 8; j++)
                    acc[i][j] = fmaf(ar[i], br[j], acc[i][j]);
        }
        __syncthreads();
    }

    #pragma unroll
    for (int i = 0; i < 8; i++) {
        int m = m0 + tr + i;
        #pragma unroll
        for (int j = 0; j < 8; j++) {
            int c = n0 + tc + j;
            out[(size_t)m * CDIM + c] = acc[i][j] + bias[c];
        }
    }
}

// ---------------------------------------------------------------------------
// Attention: one CTA per (window, head). Q/K/V + bias column staged in smem.
// Warp-per-row: QK^T via shfl-broadcast q, softmax, PV via shfl-broadcast p.
// K/V rows zero-padded to 224 so shuffles stay convergent past N=196.
// smem floats: sQ 196*32=6272 | sK 224*33=7392 | sV 7392 | sB 1184  => 88960 B
// ---------------------------------------------------------------------------
static constexpr int SMEM_ATTN_BYTES = (6272 + 7392 + 7392 + 1184) * 4;

__global__ __launch_bounds__(256, 2)
void attn_kernel(const float* __restrict__ q_global,    // (4,1,16,196,32)
                 const float* __restrict__ bias_table)  // (1183,16)
{
    extern __shared__ float sm[];
    float* sQ = sm;                 // [196][32]
    float* sK = sQ + 6272;          // [224][33]
    float* sV = sK + 7392;          // [224][33]
    float* sB = sV + 7392;          // [1183]

    const int h  = blockIdx.x;
    const int b_ = blockIdx.y;
    const int tid = threadIdx.x;
    const int lane = tid & 31, warp = tid >> 5;
    const float scale = 0.17677669529663687f;   // 32^-0.5

    const float* qp = q_global + (size_t)(((b_ >> 6) * NHEAD + h) * NTOK) * HD;
    const float* kp = g_K + (size_t)((b_ * NHEAD + h) * NTOK) * HD;
    const float* vp = g_V + (size_t)((b_ * NHEAD + h) * NTOK) * HD;

    for (int i = tid; i < NTOK * HD; i += 256) sQ[i] = qp[i] * scale;
    for (int i = tid; i < NTOK * HD; i += 256) {
        int n = i >> 5, d = i & 31;
        sK[n * 33 + d] = kp[i];
        sV[n * 33 + d] = vp[i];
    }
    for (int i = NTOK * HD + tid; i < 224 * HD; i += 256) {  // zero pad rows 196..223
        int n = i >> 5, d = i & 31;
        sK[n * 33 + d] = 0.f;
        sV[n * 33 + d] = 0.f;
    }
    for (int i = tid; i < 1183; i += 256) sB[i] = bias_table[i * NHEAD + h];
    __syncthreads();

    // per-lane key coordinates (same for every row)
    int tmc[7], hmc[7], wmc[7];
    #pragma unroll
    for (int i = 0; i < 7; i++) {
        int m = lane + 32 * i;
        tmc[i] = m / 49; int rm = m - tmc[i] * 49;
        hmc[i] = rm / 7; wmc[i] = rm - hmc[i] * 7;
    }

    for (int r = warp; r < NTOK; r += 8) {
        float qv = sQ[r * HD + lane];
        int trr = r / 49; int rr = r - trr * 49;
        int hrr = rr / 7; int wrr = rr - hrr * 7;

        float sc[7];
        #pragma unroll
        for (int i = 0; i < 7; i++) sc[i] = 0.f;
        #pragma unroll
        for (int d = 0; d < 32; d++) {
            float qd = __shfl_sync(FULLMASK, qv, d);
            #pragma unroll
            for (int i = 0; i < 7; i++)
                sc[i] = fmaf(qd, sK[(lane + 32 * i) * 33 + d], sc[i]);
        }
        #pragma unroll
        for (int i = 0; i < 7; i++) {
            int m = lane + 32 * i;
            if (m < NTOK) {
                int idx = (trr - tmc[i] + 3) * 169 + (hrr - hmc[i] + 6) * 13
                        + (wrr - wmc[i] + 6);
                sc[i] += sB[idx];
            } else {
                sc[i] = -1e30f;
            }
        }
        float mx = sc[0];
        #pragma unroll
        for (int i = 1; i < 7; i++) mx = fmaxf(mx, sc[i]);
        #pragma unroll
        for (int off = 16; off; off >>= 1)
            mx = fmaxf(mx, __shfl_xor_sync(FULLMASK, mx, off));
        float sum = 0.f;
        #pragma unroll
        for (int i = 0; i < 7; i++) { sc[i] = __expf(sc[i] - mx); sum += sc[i]; }
        #pragma unroll
        for (int off = 16; off; off >>= 1)
            sum += __shfl_xor_sync(FULLMASK, sum, off);
        float inv = 1.f / sum;

        float acc = 0.f;
        #pragma unroll
        for (int i = 0; i < 7; i++) {
            #pragma unroll
            for (int s = 0; s < 32; s++) {
                float p = __shfl_sync(FULLMASK, sc[i], s);
                acc = fmaf(p, sV[(s + 32 * i) * 33 + lane], acc);
            }
        }
        g_att[(size_t)(b_ * NTOK + r) * CDIM + h * HD + lane] = acc * inv;
    }
}

// ---------------------------------------------------------------------------
extern "C" void kernel_launch(void* const* d_in, const int* in_sizes, int n_in,
                              void* d_out, int out_size)
{
    const float* x      = (const float*)d_in[0];
    const float* qg     = (const float*)d_in[1];
    const float* kv_w   = (const float*)d_in[2];
    const float* kv_b   = (const float*)d_in[3];
    const float* proj_w = (const float*)d_in[4];
    const float* proj_b = (const float*)d_in[5];
    const float* btab   = (const float*)d_in[6];
    float* out = (float*)d_out;

    cudaFuncSetAttribute(attn_kernel,
                         cudaFuncAttributeMaxDynamicSharedMemorySize,
                         SMEM_ATTN_BYTES);

    dim3 gkv(1024 / 128, MROWS / 128);   // (8, 392)
    kv_gemm_kernel<<<gkv, 256>>>(x, kv_w, kv_b);

    dim3 gat(NHEAD, NWIN);               // (16, 256)
    attn_kernel<<<gat, 256, SMEM_ATTN_BYTES>>>(qg, btab);

    dim3 gpj(CDIM / 128, MROWS / 128);   // (4, 392)
    proj_gemm_kernel<<<gpj, 256>>>(proj_w, proj_b, out);
}

// round 5
// speedup vs baseline: 1.7448x; 1.7448x over previous
#include <cuda_runtime.h>
#include <cuda_bf16.h>
#include <cstdint>

#define FULLMASK 0xffffffffu

// Problem dims (static): B=4, B_dim=64 -> B_=256; N=196; C=512; H=16; hd=32
static constexpr int NWIN  = 256;
static constexpr int NTOK  = 196;
static constexpr int NHEAD = 16;
static constexpr int HD    = 32;
static constexpr int CDIM  = 512;
static constexpr int MROWS = NWIN * NTOK;        // 50176
static constexpr int XELT  = MROWS * CDIM;       // 25,690,112

// ---------------- static device scratch (no runtime allocation) -------------
__device__ float          g_K[XELT];             // [b_,h,n,d] fp32
__device__ float          g_V[XELT];
__device__ __nv_bfloat16  g_xh[XELT],  g_xl[XELT];       // x split
__device__ __nv_bfloat16  g_ath[XELT], g_atl[XELT];      // attn out split
__device__ __nv_bfloat16  g_kwh[2*CDIM*CDIM], g_kwl[2*CDIM*CDIM];
__device__ __nv_bfloat16  g_pwh[CDIM*CDIM],   g_pwl[CDIM*CDIM];

// ---------------- fp32 -> (bf16 hi, bf16 lo) splitter -----------------------
__global__ void split_kernel(const float* __restrict__ src,
                             __nv_bfloat16* __restrict__ hi,
                             __nv_bfloat16* __restrict__ lo, int n4)
{
    int i = blockIdx.x * blockDim.x + threadIdx.x;
    if (i >= n4) return;
    float4 v = ((const float4*)src)[i];
    __nv_bfloat16 h0 = __float2bfloat16(v.x), h1 = __float2bfloat16(v.y);
    __nv_bfloat16 h2 = __float2bfloat16(v.z), h3 = __float2bfloat16(v.w);
    __nv_bfloat16 l0 = __float2bfloat16(v.x - __bfloat162float(h0));
    __nv_bfloat16 l1 = __float2bfloat16(v.y - __bfloat162float(h1));
    __nv_bfloat16 l2 = __float2bfloat16(v.z - __bfloat162float(h2));
    __nv_bfloat16 l3 = __float2bfloat16(v.w - __bfloat162float(h3));
    __nv_bfloat162* H = (__nv_bfloat162*)hi;
    __nv_bfloat162* L = (__nv_bfloat162*)lo;
    H[2 * i]     = __halves2bfloat162(h0, h1);
    H[2 * i + 1] = __halves2bfloat162(h2, h3);
    L[2 * i]     = __halves2bfloat162(l0, l1);
    L[2 * i + 1] = __halves2bfloat162(l2, l3);
}

// ---------------- mma.sync bf16 GEMM (3-pass hi/lo) -------------------------
// C(M,Nout) = A(M,512) @ W(Nout,512)^T + bias.
// CTA tile 128x128, warp tile 64x32, K-chunk 16. Double-buffered smem.
// Smem word stride 20 per row (conflict-free for frag lds pattern).
#define MMA16816(cc, a0, a1, a2, a3, b0, b1)                                    \
    asm volatile("mma.sync.aligned.m16n8k16.row.col.f32.bf16.bf16.f32 "         \
                 "{%0,%1,%2,%3}, {%4,%5,%6,%7}, {%8,%9}, {%0,%1,%2,%3};"        \
                 : "+f"((cc)[0]), "+f"((cc)[1]), "+f"((cc)[2]), "+f"((cc)[3])   \
                 : "r"(a0), "r"(a1), "r"(a2), "r"(a3), "r"(b0), "r"(b1))

static constexpr int SROW   = 20;                 // words per smem row
static constexpr int TILE_W = 128 * SROW;         // words per 128-row tile (2560)
static constexpr int STAGE_W = 4 * TILE_W;        // Ah,Al,Wh,Wl
static constexpr int GEMM_SMEM = 512 + 2 * STAGE_W * 4;   // bytes: 512 bias + 2 stages

template <bool KV>
__global__ __launch_bounds__(256, 2)
void gemm_mma(const __nv_bfloat16* __restrict__ Ah, const __nv_bfloat16* __restrict__ Al,
              const __nv_bfloat16* __restrict__ Wh, const __nv_bfloat16* __restrict__ Wl,
              const float* __restrict__ bias, float* __restrict__ out)
{
    extern __shared__ char smg[];
    float* bias_s = (float*)smg;
    uint32_t* sw = (uint32_t*)(smg + 512);

    const int tid = threadIdx.x;
    const int wid = tid >> 5, lane = tid & 31;
    const int qr = lane >> 2, qc = lane & 3;
    const int n0 = blockIdx.x * 128, m0 = blockIdx.y * 128;
    const int mbase = (wid >> 2) * 64, nbase = (wid & 3) * 32;

    if (tid < 128) bias_s[tid] = bias[n0 + tid];

    const uint4* A4h = (const uint4*)Ah;
    const uint4* A4l = (const uint4*)Al;
    const uint4* W4h = (const uint4*)Wh;
    const uint4* W4l = (const uint4*)Wl;

    const int lr = tid >> 1;          // 0..127
    const int lh = tid & 1;           // 0..1 (uint4 half of the 32B k16 chunk)
    const size_t gaBase = (size_t)(m0 + lr) * 64 + lh;
    const size_t gwBase = (size_t)(n0 + lr) * 64 + lh;
    const int stsOff = lr * SROW + lh * 4;   // word offset (16B aligned: lr*80+lh*16)

    float c[4][4][4];
    #pragma unroll
    for (int mt = 0; mt < 4; mt++)
        #pragma unroll
        for (int nt = 0; nt < 4; nt++)
            #pragma unroll
            for (int k = 0; k < 4; k++) c[mt][nt][k] = 0.f;

    // preload chunk 0
    uint4 pa = A4h[gaBase], pl = A4l[gaBase], pwh = W4h[gwBase], pwl = W4l[gwBase];
    {
        uint32_t* st = sw;
        *(uint4*)(st + stsOff)              = pa;
        *(uint4*)(st + TILE_W + stsOff)     = pl;
        *(uint4*)(st + 2 * TILE_W + stsOff) = pwh;
        *(uint4*)(st + 3 * TILE_W + stsOff) = pwl;
    }
    __syncthreads();

    int s = 0;
    for (int kc = 0; kc < 32; kc++) {
        uint4 na, nl, nwh, nwl;
        if (kc < 31) {
            size_t ga = gaBase + (size_t)(kc + 1) * 2;
            size_t gw = gwBase + (size_t)(kc + 1) * 2;
            na = A4h[ga]; nl = A4l[ga]; nwh = W4h[gw]; nwl = W4l[gw];
        }

        const uint32_t* st = sw + s * STAGE_W;
        const uint32_t* sAh = st;
        const uint32_t* sAl = st + TILE_W;
        const uint32_t* sWh = st + 2 * TILE_W;
        const uint32_t* sWl = st + 3 * TILE_W;

        uint32_t b[4][2];
        #pragma unroll
        for (int nt = 0; nt < 4; nt++) {
            int rb = (nbase + nt * 8 + qr) * SROW + qc;
            b[nt][0] = sWh[rb]; b[nt][1] = sWh[rb + 4];
        }
        #pragma unroll
        for (int mt = 0; mt < 4; mt++) {           // pass 1: Ahi x Whi
            int ra = (mbase + mt * 16 + qr) * SROW + qc;
            uint32_t a0 = sAh[ra], a1 = sAh[ra + 8 * SROW];
            uint32_t a2 = sAh[ra + 4], a3 = sAh[ra + 8 * SROW + 4];
            #pragma unroll
            for (int nt = 0; nt < 4; nt++)
                MMA16816(c[mt][nt], a0, a1, a2, a3, b[nt][0], b[nt][1]);
        }
        #pragma unroll
        for (int mt = 0; mt < 4; mt++) {           // pass 2: Alo x Whi
            int ra = (mbase + mt * 16 + qr) * SROW + qc;
            uint32_t a0 = sAl[ra], a1 = sAl[ra + 8 * SROW];
            uint32_t a2 = sAl[ra + 4], a3 = sAl[ra + 8 * SROW + 4];
            #pragma unroll
            for (int nt = 0; nt < 4; nt++)
                MMA16816(c[mt][nt], a0, a1, a2, a3, b[nt][0], b[nt][1]);
        }
        #pragma unroll
        for (int nt = 0; nt < 4; nt++) {
            int rb = (nbase + nt * 8 + qr) * SROW + qc;
            b[nt][0] = sWl[rb]; b[nt][1] = sWl[rb + 4];
        }
        #pragma unroll
        for (int mt = 0; mt < 4; mt++) {           // pass 3: Ahi x Wlo
            int ra = (mbase + mt * 16 + qr) * SROW + qc;
            uint32_t a0 = sAh[ra], a1 = sAh[ra + 8 * SROW];
            uint32_t a2 = sAh[ra + 4], a3 = sAh[ra + 8 * SROW + 4];
            #pragma unroll
            for (int nt = 0; nt < 4; nt++)
                MMA16816(c[mt][nt], a0, a1, a2, a3, b[nt][0], b[nt][1]);
        }

        if (kc < 31) {
            __syncthreads();
            uint32_t* dn = sw + (s ^ 1) * STAGE_W;
            *(uint4*)(dn + stsOff)              = na;
            *(uint4*)(dn + TILE_W + stsOff)     = nl;
            *(uint4*)(dn + 2 * TILE_W + stsOff) = nwh;
            *(uint4*)(dn + 3 * TILE_W + stsOff) = nwl;
            __syncthreads();
            s ^= 1;
        }
    }

    // epilogue
    #pragma unroll
    for (int mt = 0; mt < 4; mt++) {
        #pragma unroll
        for (int half = 0; half < 2; half++) {
            int m = m0 + mbase + mt * 16 + qr + 8 * half;
            int b_ = m / NTOK, n = m - b_ * NTOK;
            #pragma unroll
            for (int nt = 0; nt < 4; nt++) {
                int col = n0 + nbase + nt * 8 + qc * 2;
                float2 v;
                v.x = c[mt][nt][2 * half]     + bias_s[col - n0];
                v.y = c[mt][nt][2 * half + 1] + bias_s[col - n0 + 1];
                if (KV) {
                    float* dst = (col < CDIM) ? g_K : g_V;
                    int cm = col & (CDIM - 1);
                    int h = cm >> 5, d = cm & 31;
                    *(float2*)(dst + ((size_t)((b_ * NHEAD + h) * NTOK + n)) * HD + d) = v;
                } else {
                    *(float2*)(out + (size_t)m * CDIM + col) = v;
                }
            }
        }
    }
}

// ---------------- attention (SIMT fp32, 2 rows per warp) --------------------
static constexpr int SMEM_ATTN_BYTES = (6272 + 7392 + 7392 + 1184) * 4;

__global__ __launch_bounds__(256, 2)
void attn_kernel(const float* __restrict__ q_global,    // (4,1,16,196,32)
                 const float* __restrict__ bias_table)  // (1183,16)
{
    extern __shared__ float sm[];
    float* sQ = sm;
    float* sK = sQ + 6272;
    float* sV = sK + 7392;
    float* sB = sV + 7392;

    const int h  = blockIdx.x;
    const int b_ = blockIdx.y;
    const int tid = threadIdx.x;
    const int lane = tid & 31, warp = tid >> 5;
    const float scale = 0.17677669529663687f;

    const float* qp = q_global + (size_t)(((b_ >> 6) * NHEAD + h) * NTOK) * HD;
    const float* kp = g_K + (size_t)((b_ * NHEAD + h) * NTOK) * HD;
    const float* vp = g_V + (size_t)((b_ * NHEAD + h) * NTOK) * HD;

    for (int i = tid; i < NTOK * HD; i += 256) sQ[i] = qp[i] * scale;
    for (int i = tid; i < NTOK * HD; i += 256) {
        int n = i >> 5, d = i & 31;
        sK[n * 33 + d] = kp[i];
        sV[n * 33 + d] = vp[i];
    }
    for (int i = NTOK * HD + tid; i < 224 * HD; i += 256) {
        int n = i >> 5, d = i & 31;
        sK[n * 33 + d] = 0.f;
        sV[n * 33 + d] = 0.f;
    }
    for (int i = tid; i < 1183; i += 256) sB[i] = bias_table[i * NHEAD + h];
    __syncthreads();

    int tmc[7], hmc[7], wmc[7];
    #pragma unroll
    for (int i = 0; i < 7; i++) {
        int m = lane + 32 * i;
        tmc[i] = m / 49; int rm = m - tmc[i] * 49;
        hmc[i] = rm / 7; wmc[i] = rm - hmc[i] * 7;
    }

    for (int r = warp; r < 98; r += 8) {
        const int r2 = r + 98;
        float qa = sQ[r * HD + lane];
        float qb = sQ[r2 * HD + lane];
        int ta = r / 49;  int ra = r - ta * 49;  int ha = ra / 7;  int wa = ra - ha * 7;
        int tb = r2 / 49; int rb = r2 - tb * 49; int hb = rb / 7;  int wb = rb - hb * 7;

        float s0[7], s1[7];
        #pragma unroll
        for (int i = 0; i < 7; i++) { s0[i] = 0.f; s1[i] = 0.f; }
        #pragma unroll
        for (int d = 0; d < 32; d++) {
            float q0 = __shfl_sync(FULLMASK, qa, d);
            float q1 = __shfl_sync(FULLMASK, qb, d);
            #pragma unroll
            for (int i = 0; i < 7; i++) {
                float kk = sK[(lane + 32 * i) * 33 + d];
                s0[i] = fmaf(q0, kk, s0[i]);
                s1[i] = fmaf(q1, kk, s1[i]);
            }
        }
        #pragma unroll
        for (int i = 0; i < 7; i++) {
            int m = lane + 32 * i;
            if (m < NTOK) {
                int i0 = (ta - tmc[i] + 3) * 169 + (ha - hmc[i] + 6) * 13 + (wa - wmc[i] + 6);
                int i1 = (tb - tmc[i] + 3) * 169 + (hb - hmc[i] + 6) * 13 + (wb - wmc[i] + 6);
                s0[i] += sB[i0];
                s1[i] += sB[i1];
            } else { s0[i] = -1e30f; s1[i] = -1e30f; }
        }
        float m0v = s0[0], m1v = s1[0];
        #pragma unroll
        for (int i = 1; i < 7; i++) { m0v = fmaxf(m0v, s0[i]); m1v = fmaxf(m1v, s1[i]); }
        #pragma unroll
        for (int off = 16; off; off >>= 1) {
            m0v = fmaxf(m0v, __shfl_xor_sync(FULLMASK, m0v, off));
            m1v = fmaxf(m1v, __shfl_xor_sync(FULLMASK, m1v, off));
        }
        float sum0 = 0.f, sum1 = 0.f;
        #pragma unroll
        for (int i = 0; i < 7; i++) {
            s0[i] = __expf(s0[i] - m0v); sum0 += s0[i];
            s1[i] = __expf(s1[i] - m1v); sum1 += s1[i];
        }
        #pragma unroll
        for (int off = 16; off; off >>= 1) {
            sum0 += __shfl_xor_sync(FULLMASK, sum0, off);
            sum1 += __shfl_xor_sync(FULLMASK, sum1, off);
        }
        float inv0 = 1.f / sum0, inv1 = 1.f / sum1;

        float a0 = 0.f, a1 = 0.f;
        #pragma unroll
        for (int i = 0; i < 7; i++) {
            #pragma unroll
            for (int ss = 0; ss < 32; ss++) {
                float vv = sV[(ss + 32 * i) * 33 + lane];
                a0 = fmaf(__shfl_sync(FULLMASK, s0[i], ss), vv, a0);
                a1 = fmaf(__shfl_sync(FULLMASK, s1[i], ss), vv, a1);
            }
        }
        float o0 = a0 * inv0, o1 = a1 * inv1;
        size_t oi0 = (size_t)(b_ * NTOK + r)  * CDIM + h * HD + lane;
        size_t oi1 = (size_t)(b_ * NTOK + r2) * CDIM + h * HD + lane;
        __nv_bfloat16 h0 = __float2bfloat16(o0);
        __nv_bfloat16 h1 = __float2bfloat16(o1);
        g_ath[oi0] = h0; g_atl[oi0] = __float2bfloat16(o0 - __bfloat162float(h0));
        g_ath[oi1] = h1; g_atl[oi1] = __float2bfloat16(o1 - __bfloat162float(h1));
    }
}

// ---------------------------------------------------------------------------
extern "C" void kernel_launch(void* const* d_in, const int* in_sizes, int n_in,
                              void* d_out, int out_size)
{
    const float* x      = (const float*)d_in[0];
    const float* qg     = (const float*)d_in[1];
    const float* kv_w   = (const float*)d_in[2];
    const float* kv_b   = (const float*)d_in[3];
    const float* proj_w = (const float*)d_in[4];
    const float* proj_b = (const float*)d_in[5];
    const float* btab   = (const float*)d_in[6];
    float* out = (float*)d_out;

    cudaFuncSetAttribute(attn_kernel, cudaFuncAttributeMaxDynamicSharedMemorySize,
                         SMEM_ATTN_BYTES);
    cudaFuncSetAttribute(gemm_mma<true>, cudaFuncAttributeMaxDynamicSharedMemorySize,
                         GEMM_SMEM);
    cudaFuncSetAttribute(gemm_mma<false>, cudaFuncAttributeMaxDynamicSharedMemorySize,
                         GEMM_SMEM);

    __nv_bfloat16 *xh, *xl, *kwh, *kwl, *pwh, *pwl, *ath, *atl;
    cudaGetSymbolAddress((void**)&xh,  g_xh);  cudaGetSymbolAddress((void**)&xl,  g_xl);
    cudaGetSymbolAddress((void**)&kwh, g_kwh); cudaGetSymbolAddress((void**)&kwl, g_kwl);
    cudaGetSymbolAddress((void**)&pwh, g_pwh); cudaGetSymbolAddress((void**)&pwl, g_pwl);
    cudaGetSymbolAddress((void**)&ath, g_ath); cudaGetSymbolAddress((void**)&atl, g_atl);

    int n4x = XELT / 4;
    split_kernel<<<(n4x + 255) / 256, 256>>>(x, xh, xl, n4x);
    int n4k = 2 * CDIM * CDIM / 4;
    split_kernel<<<(n4k + 255) / 256, 256>>>(kv_w, kwh, kwl, n4k);
    int n4p = CDIM * CDIM / 4;
    split_kernel<<<(n4p + 255) / 256, 256>>>(proj_w, pwh, pwl, n4p);

    dim3 gkv(2 * CDIM / 128, MROWS / 128);    // (8, 392)
    gemm_mma<true><<<gkv, 256, GEMM_SMEM>>>(xh, xl, kwh, kwl, kv_b, nullptr);

    dim3 gat(NHEAD, NWIN);                    // (16, 256)
    attn_kernel<<<gat, 256, SMEM_ATTN_BYTES>>>(qg, btab);

    dim3 gpj(CDIM / 128, MROWS / 128);        // (4, 392)
    gemm_mma<false><<<gpj, 256, GEMM_SMEM>>>(ath, atl, pwh, pwl, proj_b, out);
}

// round 8
// speedup vs baseline: 2.9438x; 1.6872x over previous
#include <cuda_runtime.h>
#include <cuda_bf16.h>
#include <cstdint>

#define FULLMASK 0xffffffffu

// Problem dims (static): B=4, B_dim=64 -> B_=256; N=196; C=512; H=16; hd=32
static constexpr int NWIN  = 256;
static constexpr int NTOK  = 196;
static constexpr int NHEAD = 16;
static constexpr int HD    = 32;
static constexpr int CDIM  = 512;
static constexpr int MROWS = NWIN * NTOK;        // 50176
static constexpr int XELT  = MROWS * CDIM;       // 25,690,112

// ---------------- static device scratch (no runtime allocation) -------------
__device__ float          g_K[XELT];             // [b_,h,n,d] fp32
__device__ float          g_V[XELT];
__device__ __nv_bfloat16  g_xh[XELT],  g_xl[XELT];       // x split
__device__ __nv_bfloat16  g_ath[XELT], g_atl[XELT];      // attn out split
__device__ __nv_bfloat16  g_kwh[2*CDIM*CDIM], g_kwl[2*CDIM*CDIM];
__device__ __nv_bfloat16  g_pwh[CDIM*CDIM],   g_pwl[CDIM*CDIM];

// ---------------- fp32 -> (bf16 hi, bf16 lo) splitter -----------------------
__global__ void split_kernel(const float* __restrict__ src,
                             __nv_bfloat16* __restrict__ hi,
                             __nv_bfloat16* __restrict__ lo, int n4)
{
    int i = blockIdx.x * blockDim.x + threadIdx.x;
    if (i >= n4) return;
    float4 v = ((const float4*)src)[i];
    __nv_bfloat16 h0 = __float2bfloat16(v.x), h1 = __float2bfloat16(v.y);
    __nv_bfloat16 h2 = __float2bfloat16(v.z), h3 = __float2bfloat16(v.w);
    __nv_bfloat16 l0 = __float2bfloat16(v.x - __bfloat162float(h0));
    __nv_bfloat16 l1 = __float2bfloat16(v.y - __bfloat162float(h1));
    __nv_bfloat16 l2 = __float2bfloat16(v.z - __bfloat162float(h2));
    __nv_bfloat16 l3 = __float2bfloat16(v.w - __bfloat162float(h3));
    __nv_bfloat162* H = (__nv_bfloat162*)hi;
    __nv_bfloat162* L = (__nv_bfloat162*)lo;
    H[2 * i]     = __halves2bfloat162(h0, h1);
    H[2 * i + 1] = __halves2bfloat162(h2, h3);
    L[2 * i]     = __halves2bfloat162(l0, l1);
    L[2 * i + 1] = __halves2bfloat162(l2, l3);
}

// ---------------- mma.sync plumbing ----------------------------------------
#define MMA16816(cc, a0, a1, a2, a3, b0, b1)                                    \
    asm volatile("mma.sync.aligned.m16n8k16.row.col.f32.bf16.bf16.f32 "         \
                 "{%0,%1,%2,%3}, {%4,%5,%6,%7}, {%8,%9}, {%0,%1,%2,%3};"        \
                 : "+f"((cc)[0]), "+f"((cc)[1]), "+f"((cc)[2]), "+f"((cc)[3])   \
                 : "r"(a0), "r"(a1), "r"(a2), "r"(a3), "r"(b0), "r"(b1))

__device__ __forceinline__ uint32_t pack_bf2(__nv_bfloat16 a, __nv_bfloat16 b) {
    uint16_t ua = *(uint16_t*)&a, ub = *(uint16_t*)&b;
    return ((uint32_t)ub << 16) | ua;      // low half = a (smaller k index)
}

// ---------------- mma.sync bf16 GEMM (3-pass hi/lo) -------------------------
static constexpr int SROW   = 20;
static constexpr int TILE_W = 128 * SROW;
static constexpr int STAGE_W = 4 * TILE_W;
static constexpr int GEMM_SMEM = 512 + 2 * STAGE_W * 4;

template <bool KV>
__global__ __launch_bounds__(256, 2)
void gemm_mma(const __nv_bfloat16* __restrict__ Ah, const __nv_bfloat16* __restrict__ Al,
              const __nv_bfloat16* __restrict__ Wh, const __nv_bfloat16* __restrict__ Wl,
              const float* __restrict__ bias, float* __restrict__ out)
{
    extern __shared__ char smg[];
    float* bias_s = (float*)smg;
    uint32_t* sw = (uint32_t*)(smg + 512);

    const int tid = threadIdx.x;
    const int wid = tid >> 5, lane = tid & 31;
    const int qr = lane >> 2, qc = lane & 3;
    const int n0 = blockIdx.x * 128, m0 = blockIdx.y * 128;
    const int mbase = (wid >> 2) * 64, nbase = (wid & 3) * 32;

    if (tid < 128) bias_s[tid] = bias[n0 + tid];

    const uint4* A4h = (const uint4*)Ah;
    const uint4* A4l = (const uint4*)Al;
    const uint4* W4h = (const uint4*)Wh;
    const uint4* W4l = (const uint4*)Wl;

    const int lr = tid >> 1;
    const int lh = tid & 1;
    const size_t gaBase = (size_t)(m0 + lr) * 64 + lh;
    const size_t gwBase = (size_t)(n0 + lr) * 64 + lh;
    const int stsOff = lr * SROW + lh * 4;

    float c[4][4][4];
    #pragma unroll
    for (int mt = 0; mt < 4; mt++)
        #pragma unroll
        for (int nt = 0; nt < 4; nt++)
            #pragma unroll
            for (int k = 0; k < 4; k++) c[mt][nt][k] = 0.f;

    uint4 pa = A4h[gaBase], plo = A4l[gaBase], pwh = W4h[gwBase], pwl = W4l[gwBase];
    {
        uint32_t* st = sw;
        *(uint4*)(st + stsOff)              = pa;
        *(uint4*)(st + TILE_W + stsOff)     = plo;
        *(uint4*)(st + 2 * TILE_W + stsOff) = pwh;
        *(uint4*)(st + 3 * TILE_W + stsOff) = pwl;
    }
    __syncthreads();

    int s = 0;
    for (int kc = 0; kc < 32; kc++) {
        uint4 na, nl, nwh, nwl;
        if (kc < 31) {
            size_t ga = gaBase + (size_t)(kc + 1) * 2;
            size_t gw = gwBase + (size_t)(kc + 1) * 2;
            na = A4h[ga]; nl = A4l[ga]; nwh = W4h[gw]; nwl = W4l[gw];
        }

        const uint32_t* st  = sw + s * STAGE_W;
        const uint32_t* sAh = st;
        const uint32_t* sAl = st + TILE_W;
        const uint32_t* sWh = st + 2 * TILE_W;
        const uint32_t* sWl = st + 3 * TILE_W;

        uint32_t bh[4][2], bl[4][2];
        #pragma unroll
        for (int nt = 0; nt < 4; nt++) {
            int rb = (nbase + nt * 8 + qr) * SROW + qc;
            bh[nt][0] = sWh[rb]; bh[nt][1] = sWh[rb + 4];
            bl[nt][0] = sWl[rb]; bl[nt][1] = sWl[rb + 4];
        }
        #pragma unroll
        for (int mt = 0; mt < 4; mt++) {
            int ra_ = (mbase + mt * 16 + qr) * SROW + qc;
            uint32_t a0 = sAh[ra_], a1 = sAh[ra_ + 8 * SROW];
            uint32_t a2 = sAh[ra_ + 4], a3 = sAh[ra_ + 8 * SROW + 4];
            uint32_t e0 = sAl[ra_], e1 = sAl[ra_ + 8 * SROW];
            uint32_t e2 = sAl[ra_ + 4], e3 = sAl[ra_ + 8 * SROW + 4];
            #pragma unroll
            for (int nt = 0; nt < 4; nt++)
                MMA16816(c[mt][nt], a0, a1, a2, a3, bh[nt][0], bh[nt][1]);
            #pragma unroll
            for (int nt = 0; nt < 4; nt++)
                MMA16816(c[mt][nt], e0, e1, e2, e3, bh[nt][0], bh[nt][1]);
            #pragma unroll
            for (int nt = 0; nt < 4; nt++)
                MMA16816(c[mt][nt], a0, a1, a2, a3, bl[nt][0], bl[nt][1]);
        }

        if (kc < 31) {
            __syncthreads();
            uint32_t* dn = sw + (s ^ 1) * STAGE_W;
            *(uint4*)(dn + stsOff)              = na;
            *(uint4*)(dn + TILE_W + stsOff)     = nl;
            *(uint4*)(dn + 2 * TILE_W + stsOff) = nwh;
            *(uint4*)(dn + 3 * TILE_W + stsOff) = nwl;
            __syncthreads();
            s ^= 1;
        }
    }

    #pragma unroll
    for (int mt = 0; mt < 4; mt++) {
        #pragma unroll
        for (int half = 0; half < 2; half++) {
            int m = m0 + mbase + mt * 16 + qr + 8 * half;
            int b_ = m / NTOK, n = m - b_ * NTOK;
            #pragma unroll
            for (int nt = 0; nt < 4; nt++) {
                int col = n0 + nbase + nt * 8 + qc * 2;
                float2 v;
                v.x = c[mt][nt][2 * half]     + bias_s[col - n0];
                v.y = c[mt][nt][2 * half + 1] + bias_s[col - n0 + 1];
                if (KV) {
                    float* dst = (col < CDIM) ? g_K : g_V;
                    int cm = col & (CDIM - 1);
                    int h = cm >> 5, d = cm & 31;
                    *(float2*)(dst + ((size_t)((b_ * NHEAD + h) * NTOK + n)) * HD + d) = v;
                } else {
                    *(float2*)(out + (size_t)m * CDIM + col) = v;
                }
            }
        }
    }
}

// ---------------- mma.sync attention ----------------------------------------
// One CTA per (window, head). Tokens padded to 224. Warp owns 16-row S strips.
// smem (words): Qh 4480 | Ql 4480 | Kh 4480 | Kl 4480 | Vh 4480 | Vl 4480 |
//               sBias 1184 | colTerm 224   => 28288 words = 113152 B
static constexpr int ATTN_SMEM_B = 28288 * 4;

__global__ __launch_bounds__(256, 1)
void attn_mma(const float* __restrict__ q_global,
              const float* __restrict__ bias_table)
{
    extern __shared__ float sm[];
    __nv_bfloat16* Qh = (__nv_bfloat16*)(sm);
    __nv_bfloat16* Ql = (__nv_bfloat16*)(sm + 4480);
    __nv_bfloat16* Kh = (__nv_bfloat16*)(sm + 8960);
    __nv_bfloat16* Kl = (__nv_bfloat16*)(sm + 13440);
    __nv_bfloat16* Vh = (__nv_bfloat16*)(sm + 17920);
    __nv_bfloat16* Vl = (__nv_bfloat16*)(sm + 22400);
    float* sBias = sm + 26880;            // 1183 used
    int*   sCT   = (int*)(sm + 28064);    // 224

    const int h = blockIdx.x, b_ = blockIdx.y;
    const int tid = threadIdx.x, lane = tid & 31, wid = tid >> 5;
    const int qr = lane >> 2, qc = lane & 3;

    const float* qp = q_global + (size_t)(((b_ >> 6) * NHEAD + h) * NTOK) * HD;
    const float* kp = g_K + (size_t)((b_ * NHEAD + h) * NTOK) * HD;
    const float* vp = g_V + (size_t)((b_ * NHEAD + h) * NTOK) * HD;

    for (int i = tid; i < 224 * 32; i += 256) {
        int row = i >> 5, d = i & 31;
        bool ok = row < NTOK;
        float qv = ok ? qp[row * 32 + d] * 0.17677669529663687f : 0.f;
        __nv_bfloat16 hh = __float2bfloat16(qv);
        Qh[row * 40 + d] = hh;
        Ql[row * 40 + d] = __float2bfloat16(qv - __bfloat162float(hh));
        float kv = ok ? kp[row * 32 + d] : 0.f;
        hh = __float2bfloat16(kv);
        Kh[row * 40 + d] = hh;
        Kl[row * 40 + d] = __float2bfloat16(kv - __bfloat162float(hh));
        float vv = ok ? vp[row * 32 + d] : 0.f;
        hh = __float2bfloat16(vv);
        int pi = (row >> 1) * 80 + d * 2 + (row & 1);   // packed token pairs
        Vh[pi] = hh;
        Vl[pi] = __float2bfloat16(vv - __bfloat162float(hh));
    }
    for (int i = tid; i < 1183; i += 256) sBias[i] = bias_table[i * NHEAD + h];
    for (int cix = tid; cix < 224; cix += 256) {
        int v = 0;
        if (cix < NTOK) {
            int t = cix / 49, r = cix - t * 49, hh = r / 7, w = r - hh * 7;
            v = -(t * 169 + hh * 13 + w);
        }
        sCT[cix] = v;
    }
    __syncthreads();

    const uint32_t* Qh32 = (const uint32_t*)Qh;
    const uint32_t* Ql32 = (const uint32_t*)Ql;
    const uint32_t* Kh32 = (const uint32_t*)Kh;
    const uint32_t* Kl32 = (const uint32_t*)Kl;
    const uint32_t* Vh32 = (const uint32_t*)Vh;
    const uint32_t* Vl32 = (const uint32_t*)Vl;

    for (int strip = wid; strip < 14; strip += 8) {
        const int r0 = strip * 16;
        const int ra = r0 + qr, rb = ra + 8;
        int rtA = 591, rtB = 591;
        if (ra < NTOK) { int t = ra / 49, r = ra - t * 49, hh = r / 7, w = r - hh * 7;
                         rtA = t * 169 + hh * 13 + w + 591; }
        if (rb < NTOK) { int t = rb / 49, r = rb - t * 49, hh = r / 7, w = r - hh * 7;
                         rtB = t * 169 + hh * 13 + w + 591; }

        uint32_t qa[2][4], qe[2][4];
        #pragma unroll
        for (int kc = 0; kc < 2; kc++) {
            int b0 = (r0 + qr) * 20 + kc * 8 + qc;
            qa[kc][0] = Qh32[b0];       qa[kc][1] = Qh32[b0 + 160];
            qa[kc][2] = Qh32[b0 + 4];   qa[kc][3] = Qh32[b0 + 164];
            qe[kc][0] = Ql32[b0];       qe[kc][1] = Ql32[b0 + 160];
            qe[kc][2] = Ql32[b0 + 4];   qe[kc][3] = Ql32[b0 + 164];
        }

        float cc[28][4];
        #pragma unroll
        for (int nt = 0; nt < 28; nt++)
            #pragma unroll
            for (int k = 0; k < 4; k++) cc[nt][k] = 0.f;

        #pragma unroll
        for (int nt = 0; nt < 28; nt++) {
            int kb = (nt * 8 + qr) * 20 + qc;
            uint32_t h0 = Kh32[kb], h1 = Kh32[kb + 4], h2 = Kh32[kb + 8], h3 = Kh32[kb + 12];
            uint32_t l0 = Kl32[kb], l1 = Kl32[kb + 4], l2 = Kl32[kb + 8], l3 = Kl32[kb + 12];
            MMA16816(cc[nt], qa[0][0], qa[0][1], qa[0][2], qa[0][3], h0, h1);
            MMA16816(cc[nt], qa[1][0], qa[1][1], qa[1][2], qa[1][3], h2, h3);
            MMA16816(cc[nt], qe[0][0], qe[0][1], qe[0][2], qe[0][3], h0, h1);
            MMA16816(cc[nt], qe[1][0], qe[1][1], qe[1][2], qe[1][3], h2, h3);
            MMA16816(cc[nt], qa[0][0], qa[0][1], qa[0][2], qa[0][3], l0, l1);
            MMA16816(cc[nt], qa[1][0], qa[1][1], qa[1][2], qa[1][3], l2, l3);
        }

        // bias + mask + row max
        float mA = -1e30f, mB = -1e30f;
        #pragma unroll
        for (int nt = 0; nt < 28; nt++) {
            int c0 = nt * 8 + qc * 2;
            if (c0 < NTOK) {
                int ct = sCT[c0];
                cc[nt][0] += sBias[rtA + ct];
                cc[nt][2] += sBias[rtB + ct];
            } else { cc[nt][0] = -1e30f; cc[nt][2] = -1e30f; }
            if (c0 + 1 < NTOK) {
                int ct = sCT[c0 + 1];
                cc[nt][1] += sBias[rtA + ct];
                cc[nt][3] += sBias[rtB + ct];
            } else { cc[nt][1] = -1e30f; cc[nt][3] = -1e30f; }
            mA = fmaxf(mA, fmaxf(cc[nt][0], cc[nt][1]));
            mB = fmaxf(mB, fmaxf(cc[nt][2], cc[nt][3]));
        }
        mA = fmaxf(mA, __shfl_xor_sync(FULLMASK, mA, 1));
        mA = fmaxf(mA, __shfl_xor_sync(FULLMASK, mA, 2));
        mB = fmaxf(mB, __shfl_xor_sync(FULLMASK, mB, 1));
        mB = fmaxf(mB, __shfl_xor_sync(FULLMASK, mB, 2));

        float sumA = 0.f, sumB = 0.f;
        #pragma unroll
        for (int nt = 0; nt < 28; nt++) {
            cc[nt][0] = __expf(cc[nt][0] - mA); sumA += cc[nt][0];
            cc[nt][1] = __expf(cc[nt][1] - mA); sumA += cc[nt][1];
            cc[nt][2] = __expf(cc[nt][2] - mB); sumB += cc[nt][2];
            cc[nt][3] = __expf(cc[nt][3] - mB); sumB += cc[nt][3];
        }
        sumA += __shfl_xor_sync(FULLMASK, sumA, 1);
        sumA += __shfl_xor_sync(FULLMASK, sumA, 2);
        sumB += __shfl_xor_sync(FULLMASK, sumB, 1);
        sumB += __shfl_xor_sync(FULLMASK, sumB, 2);
        float iA = 1.f / sumA, iB = 1.f / sumB;

        // repack P (C-frag pairs -> A-frags), hi/lo
        uint32_t ph[14][4], pl[14][4];
        #pragma unroll
        for (int t = 0; t < 14; t++) {
            #pragma unroll
            for (int half = 0; half < 2; half++) {       // half: 0 -> rows qr, 1 -> qr+8
                float x0 = cc[2 * t][2 * half], x1 = cc[2 * t][2 * half + 1];
                float y0 = cc[2 * t + 1][2 * half], y1 = cc[2 * t + 1][2 * half + 1];
                __nv_bfloat16 hx0 = __float2bfloat16(x0), hx1 = __float2bfloat16(x1);
                __nv_bfloat16 hy0 = __float2bfloat16(y0), hy1 = __float2bfloat16(y1);
                ph[t][half]     = pack_bf2(hx0, hx1);
                ph[t][half + 2] = pack_bf2(hy0, hy1);
                pl[t][half]     = pack_bf2(__float2bfloat16(x0 - __bfloat162float(hx0)),
                                           __float2bfloat16(x1 - __bfloat162float(hx1)));
                pl[t][half + 2] = pack_bf2(__float2bfloat16(y0 - __bfloat162float(hy0)),
                                           __float2bfloat16(y1 - __bfloat162float(hy1)));
            }
        }

        float oo[4][4];
        #pragma unroll
        for (int n2 = 0; n2 < 4; n2++)
            #pragma unroll
            for (int k = 0; k < 4; k++) oo[n2][k] = 0.f;

        #pragma unroll
        for (int t = 0; t < 14; t++) {
            #pragma unroll
            for (int n2 = 0; n2 < 4; n2++) {
                int vb = (t * 8 + qc) * 40 + n2 * 8 + qr;
                uint32_t bh0 = Vh32[vb], bh1 = Vh32[vb + 160];
                uint32_t bl0 = Vl32[vb], bl1 = Vl32[vb + 160];
                MMA16816(oo[n2], ph[t][0], ph[t][1], ph[t][2], ph[t][3], bh0, bh1);
                MMA16816(oo[n2], pl[t][0], pl[t][1], pl[t][2], pl[t][3], bh0, bh1);
                MMA16816(oo[n2], ph[t][0], ph[t][1], ph[t][2], ph[t][3], bl0, bl1);
            }
        }

        if (ra < NTOK) {
            size_t wb = ((size_t)(b_ * NTOK + ra)) * CDIM + h * HD;
            #pragma unroll
            for (int n2 = 0; n2 < 4; n2++) {
                int col = n2 * 8 + qc * 2;
                float x = oo[n2][0] * iA, y = oo[n2][1] * iA;
                __nv_bfloat16 hx = __float2bfloat16(x), hy = __float2bfloat16(y);
                ((uint32_t*)g_ath)[(wb + col) >> 1] = pack_bf2(hx, hy);
                ((uint32_t*)g_atl)[(wb + col) >> 1] =
                    pack_bf2(__float2bfloat16(x - __bfloat162float(hx)),
                             __float2bfloat16(y - __bfloat162float(hy)));
            }
        }
        if (rb < NTOK) {
            size_t wb = ((size_t)(b_ * NTOK + rb)) * CDIM + h * HD;
            #pragma unroll
            for (int n2 = 0; n2 < 4; n2++) {
                int col = n2 * 8 + qc * 2;
                float x = oo[n2][2] * iB, y = oo[n2][3] * iB;
                __nv_bfloat16 hx = __float2bfloat16(x), hy = __float2bfloat16(y);
                ((uint32_t*)g_ath)[(wb + col) >> 1] = pack_bf2(hx, hy);
                ((uint32_t*)g_atl)[(wb + col) >> 1] =
                    pack_bf2(__float2bfloat16(x - __bfloat162float(hx)),
                             __float2bfloat16(y - __bfloat162float(hy)));
            }
        }
    }
}

// ---------------------------------------------------------------------------
extern "C" void kernel_launch(void* const* d_in, const int* in_sizes, int n_in,
                              void* d_out, int out_size)
{
    const float* x      = (const float*)d_in[0];
    const float* qg     = (const float*)d_in[1];
    const float* kv_w   = (const float*)d_in[2];
    const float* kv_b   = (const float*)d_in[3];
    const float* proj_w = (const float*)d_in[4];
    const float* proj_b = (const float*)d_in[5];
    const float* btab   = (const float*)d_in[6];
    float* out = (float*)d_out;

    cudaFuncSetAttribute(attn_mma, cudaFuncAttributeMaxDynamicSharedMemorySize,
                         ATTN_SMEM_B);
    cudaFuncSetAttribute(gemm_mma<true>, cudaFuncAttributeMaxDynamicSharedMemorySize,
                         GEMM_SMEM);
    cudaFuncSetAttribute(gemm_mma<false>, cudaFuncAttributeMaxDynamicSharedMemorySize,
                         GEMM_SMEM);

    __nv_bfloat16 *xh, *xl, *kwh, *kwl, *pwh, *pwl, *ath, *atl;
    cudaGetSymbolAddress((void**)&xh,  g_xh);  cudaGetSymbolAddress((void**)&xl,  g_xl);
    cudaGetSymbolAddress((void**)&kwh, g_kwh); cudaGetSymbolAddress((void**)&kwl, g_kwl);
    cudaGetSymbolAddress((void**)&pwh, g_pwh); cudaGetSymbolAddress((void**)&pwl, g_pwl);
    cudaGetSymbolAddress((void**)&ath, g_ath); cudaGetSymbolAddress((void**)&atl, g_atl);

    int n4x = XELT / 4;
    split_kernel<<<(n4x + 255) / 256, 256>>>(x, xh, xl, n4x);
    int n4k = 2 * CDIM * CDIM / 4;
    split_kernel<<<(n4k + 255) / 256, 256>>>(kv_w, kwh, kwl, n4k);
    int n4p = CDIM * CDIM / 4;
    split_kernel<<<(n4p + 255) / 256, 256>>>(proj_w, pwh, pwl, n4p);

    dim3 gkv(2 * CDIM / 128, MROWS / 128);    // (8, 392)
    gemm_mma<true><<<gkv, 256, GEMM_SMEM>>>(xh, xl, kwh, kwl, kv_b, nullptr);

    dim3 gat(NHEAD, NWIN);                    // (16, 256)
    attn_mma<<<gat, 256, ATTN_SMEM_B>>>(qg, btab);

    dim3 gpj(CDIM / 128, MROWS / 128);        // (4, 392)
    gemm_mma<false><<<gpj, 256, GEMM_SMEM>>>(ath, atl, pwh, pwl, proj_b, out);
}

// round 9
// speedup vs baseline: 3.2458x; 1.1026x over previous
#include <cuda_runtime.h>
#include <cuda_bf16.h>
#include <cstdint>

#define FULLMASK 0xffffffffu

// Problem dims (static): B=4, B_dim=64 -> B_=256; N=196; C=512; H=16; hd=32
static constexpr int NWIN  = 256;
static constexpr int NTOK  = 196;
static constexpr int NHEAD = 16;
static constexpr int HD    = 32;
static constexpr int CDIM  = 512;
static constexpr int MROWS = NWIN * NTOK;        // 50176
static constexpr int XELT  = MROWS * CDIM;       // 25,690,112

// ---------------- static device scratch (no runtime allocation) -------------
__device__ float          g_K[XELT];             // [b_,h,n,d] fp32
__device__ float          g_V[XELT];
__device__ __nv_bfloat16  g_xh[XELT],  g_xl[XELT];       // x split
__device__ __nv_bfloat16  g_ath[XELT], g_atl[XELT];      // attn out split
__device__ __nv_bfloat16  g_kwh[2*CDIM*CDIM], g_kwl[2*CDIM*CDIM];
__device__ __nv_bfloat16  g_pwh[CDIM*CDIM],   g_pwl[CDIM*CDIM];

// ---------------- fp32 -> (bf16 hi, bf16 lo) splitter -----------------------
__global__ void split_kernel(const float* __restrict__ src,
                             __nv_bfloat16* __restrict__ hi,
                             __nv_bfloat16* __restrict__ lo, int n4)
{
    int i = blockIdx.x * blockDim.x + threadIdx.x;
    if (i >= n4) return;
    float4 v = ((const float4*)src)[i];
    __nv_bfloat16 h0 = __float2bfloat16(v.x), h1 = __float2bfloat16(v.y);
    __nv_bfloat16 h2 = __float2bfloat16(v.z), h3 = __float2bfloat16(v.w);
    __nv_bfloat16 l0 = __float2bfloat16(v.x - __bfloat162float(h0));
    __nv_bfloat16 l1 = __float2bfloat16(v.y - __bfloat162float(h1));
    __nv_bfloat16 l2 = __float2bfloat16(v.z - __bfloat162float(h2));
    __nv_bfloat16 l3 = __float2bfloat16(v.w - __bfloat162float(h3));
    __nv_bfloat162* H = (__nv_bfloat162*)hi;
    __nv_bfloat162* L = (__nv_bfloat162*)lo;
    H[2 * i]     = __halves2bfloat162(h0, h1);
    H[2 * i + 1] = __halves2bfloat162(h2, h3);
    L[2 * i]     = __halves2bfloat162(l0, l1);
    L[2 * i + 1] = __halves2bfloat162(l2, l3);
}

// ---------------- mma.sync plumbing ----------------------------------------
#define MMA16816(cc, a0, a1, a2, a3, b0, b1)                                    \
    asm volatile("mma.sync.aligned.m16n8k16.row.col.f32.bf16.bf16.f32 "         \
                 "{%0,%1,%2,%3}, {%4,%5,%6,%7}, {%8,%9}, {%0,%1,%2,%3};"        \
                 : "+f"((cc)[0]), "+f"((cc)[1]), "+f"((cc)[2]), "+f"((cc)[3])   \
                 : "r"(a0), "r"(a1), "r"(a2), "r"(a3), "r"(b0), "r"(b1))

#define LDSM_X4(r0, r1, r2, r3, addr)                                           \
    asm volatile("ldmatrix.sync.aligned.m8n8.x4.shared.b16 {%0,%1,%2,%3}, [%4];"\
        : "=r"(r0), "=r"(r1), "=r"(r2), "=r"(r3) : "r"(addr))

#define CP16(saddr, gptr)                                                       \
    asm volatile("cp.async.cg.shared.global [%0], [%1], 16;"                    \
        :: "r"(saddr), "l"(gptr) : "memory")

__device__ __forceinline__ uint32_t smem_u32(const void* p) {
    uint32_t a;
    asm("{ .reg .u64 t; cvta.to.shared.u64 t, %1; cvt.u32.u64 %0, t; }"
        : "=r"(a) : "l"(p));
    return a;
}

__device__ __forceinline__ uint32_t pack_bf2(__nv_bfloat16 a, __nv_bfloat16 b) {
    uint16_t ua = *(uint16_t*)&a, ub = *(uint16_t*)&b;
    return ((uint32_t)ub << 16) | ua;      // low half = a (smaller k index)
}

// ---------------- mma.sync bf16 GEMM (3-pass hi/lo, cp.async + ldmatrix) ----
// CTA tile 128x128, K-chunk 32, 2-stage cp.async pipeline.
// Smem per tile: 128 rows x 20 words (16 data + 4 pad). Tiles: Ah,Al,Wh,Wl.
static constexpr int SROW    = 20;
static constexpr int TILE_W  = 128 * SROW;           // 2560 words
static constexpr int TILE_B  = TILE_W * 4;           // 10240 bytes
static constexpr int STAGE_B = 4 * TILE_B;           // 40960 bytes
static constexpr int GEMM_SMEM = 512 + 2 * STAGE_B;  // 82432 bytes

template <bool KV>
__global__ __launch_bounds__(256, 2)
void gemm_mma(const __nv_bfloat16* __restrict__ Ah, const __nv_bfloat16* __restrict__ Al,
              const __nv_bfloat16* __restrict__ Wh, const __nv_bfloat16* __restrict__ Wl,
              const float* __restrict__ bias, float* __restrict__ out)
{
    extern __shared__ char smg[];
    float* bias_s = (float*)smg;
    const uint32_t swb = smem_u32(smg + 512);

    const int tid = threadIdx.x;
    const int wid = tid >> 5, lane = tid & 31;
    const int qr = lane >> 2, qc = lane & 3;
    const int n0 = blockIdx.x * 128, m0 = blockIdx.y * 128;
    const int mbase = (wid >> 2) * 64, nbase = (wid & 3) * 32;

    if (tid < 128) bias_s[tid] = bias[n0 + tid];

    const uint4* A4h = (const uint4*)Ah;
    const uint4* A4l = (const uint4*)Al;
    const uint4* W4h = (const uint4*)Wh;
    const uint4* W4l = (const uint4*)Wl;

    // per-thread cp.async geometry (2 x 16B chunks per tile per stage)
    const int r0i = (tid * 2) >> 2, c40 = (tid * 2) & 3;
    const int r1i = (tid * 2 + 1) >> 2, c41 = (tid * 2 + 1) & 3;

    auto issue_stage = [&](int kc, int s) {
        uint32_t sb = swb + s * STAGE_B;
        {
            uint32_t so = (uint32_t)(r0i * SROW + c40 * 4) * 4;
            size_t ga = (size_t)(m0 + r0i) * 64 + kc * 4 + c40;
            size_t gw = (size_t)(n0 + r0i) * 64 + kc * 4 + c40;
            CP16(sb + so,              A4h + ga);
            CP16(sb + TILE_B + so,     A4l + ga);
            CP16(sb + 2 * TILE_B + so, W4h + gw);
            CP16(sb + 3 * TILE_B + so, W4l + gw);
        }
        {
            uint32_t so = (uint32_t)(r1i * SROW + c41 * 4) * 4;
            size_t ga = (size_t)(m0 + r1i) * 64 + kc * 4 + c41;
            size_t gw = (size_t)(n0 + r1i) * 64 + kc * 4 + c41;
            CP16(sb + so,              A4h + ga);
            CP16(sb + TILE_B + so,     A4l + ga);
            CP16(sb + 2 * TILE_B + so, W4h + gw);
            CP16(sb + 3 * TILE_B + so, W4l + gw);
        }
        asm volatile("cp.async.commit_group;" ::: "memory");
    };

    float c[4][4][4];
    #pragma unroll
    for (int mt = 0; mt < 4; mt++)
        #pragma unroll
        for (int nt = 0; nt < 4; nt++)
            #pragma unroll
            for (int k = 0; k < 4; k++) c[mt][nt][k] = 0.f;

    issue_stage(0, 0);
    issue_stage(1, 1);

    // ldmatrix lane addressing (byte offsets within a tile)
    const int aRow = lane & 15, aKh = lane >> 4;                  // A frags
    const int wSub = lane >> 3;
    const int wRow = ((wSub >> 1) * 8) + (lane & 7), wKh = wSub & 1;  // W frags

    for (int kc = 0; kc < 16; kc++) {
        const int s = kc & 1;
        if (kc == 15) asm volatile("cp.async.wait_group 0;" ::: "memory");
        else          asm volatile("cp.async.wait_group 1;" ::: "memory");
        __syncthreads();

        const uint32_t tb = swb + s * STAGE_B;
        #pragma unroll
        for (int ks = 0; ks < 2; ks++) {
            uint32_t bh[4][2], bl[4][2];
            #pragma unroll
            for (int np = 0; np < 2; np++) {
                uint32_t wa = tb + 2 * TILE_B +
                    (uint32_t)(((nbase + np * 16 + wRow) * SROW + ks * 8 + wKh * 4) * 4);
                LDSM_X4(bh[np*2][0], bh[np*2][1], bh[np*2+1][0], bh[np*2+1][1], wa);
                LDSM_X4(bl[np*2][0], bl[np*2][1], bl[np*2+1][0], bl[np*2+1][1],
                        wa + TILE_B);
            }
            #pragma unroll
            for (int mt = 0; mt < 4; mt++) {
                uint32_t aa = tb +
                    (uint32_t)(((mbase + mt * 16 + aRow) * SROW + ks * 8 + aKh * 4) * 4);
                uint32_t a0, a1, a2, a3, e0, e1, e2, e3;
                LDSM_X4(a0, a1, a2, a3, aa);
                LDSM_X4(e0, e1, e2, e3, aa + TILE_B);
                #pragma unroll
                for (int nt = 0; nt < 4; nt++)
                    MMA16816(c[mt][nt], a0, a1, a2, a3, bh[nt][0], bh[nt][1]);
                #pragma unroll
                for (int nt = 0; nt < 4; nt++)
                    MMA16816(c[mt][nt], e0, e1, e2, e3, bh[nt][0], bh[nt][1]);
                #pragma unroll
                for (int nt = 0; nt < 4; nt++)
                    MMA16816(c[mt][nt], a0, a1, a2, a3, bl[nt][0], bl[nt][1]);
            }
        }
        __syncthreads();
        if (kc + 2 < 16) issue_stage(kc + 2, s);
    }

    // epilogue
    #pragma unroll
    for (int mt = 0; mt < 4; mt++) {
        #pragma unroll
        for (int half = 0; half < 2; half++) {
            int m = m0 + mbase + mt * 16 + qr + 8 * half;
            int b_ = m / NTOK, n = m - b_ * NTOK;
            #pragma unroll
            for (int nt = 0; nt < 4; nt++) {
                int col = n0 + nbase + nt * 8 + qc * 2;
                float2 v;
                v.x = c[mt][nt][2 * half]     + bias_s[col - n0];
                v.y = c[mt][nt][2 * half + 1] + bias_s[col - n0 + 1];
                if (KV) {
                    float* dst = (col < CDIM) ? g_K : g_V;
                    int cm = col & (CDIM - 1);
                    int h = cm >> 5, d = cm & 31;
                    *(float2*)(dst + ((size_t)((b_ * NHEAD + h) * NTOK + n)) * HD + d) = v;
                } else {
                    *(float2*)(out + (size_t)m * CDIM + col) = v;
                }
            }
        }
    }
}

// ---------------- mma.sync attention ----------------------------------------
// One CTA per (window, head). Tokens padded to 224. Warp owns 16-row S strips.
static constexpr int ATTN_SMEM_B = 28288 * 4;

__global__ __launch_bounds__(256, 1)
void attn_mma(const float* __restrict__ q_global,
              const float* __restrict__ bias_table)
{
    extern __shared__ float sm[];
    __nv_bfloat16* Qh = (__nv_bfloat16*)(sm);
    __nv_bfloat16* Ql = (__nv_bfloat16*)(sm + 4480);
    __nv_bfloat16* Kh = (__nv_bfloat16*)(sm + 8960);
    __nv_bfloat16* Kl = (__nv_bfloat16*)(sm + 13440);
    __nv_bfloat16* Vh = (__nv_bfloat16*)(sm + 17920);
    __nv_bfloat16* Vl = (__nv_bfloat16*)(sm + 22400);
    float* sBias = sm + 26880;            // 1183 used
    int*   sCT   = (int*)(sm + 28064);    // 224

    const int h = blockIdx.x, b_ = blockIdx.y;
    const int tid = threadIdx.x, lane = tid & 31, wid = tid >> 5;
    const int qr = lane >> 2, qc = lane & 3;

    const float* qp = q_global + (size_t)(((b_ >> 6) * NHEAD + h) * NTOK) * HD;
    const float* kp = g_K + (size_t)((b_ * NHEAD + h) * NTOK) * HD;
    const float* vp = g_V + (size_t)((b_ * NHEAD + h) * NTOK) * HD;

    for (int i = tid; i < 224 * 32; i += 256) {
        int row = i >> 5, d = i & 31;
        bool ok = row < NTOK;
        float qv = ok ? qp[row * 32 + d] * 0.17677669529663687f : 0.f;
        __nv_bfloat16 hh = __float2bfloat16(qv);
        Qh[row * 40 + d] = hh;
        Ql[row * 40 + d] = __float2bfloat16(qv - __bfloat162float(hh));
        float kv = ok ? kp[row * 32 + d] : 0.f;
        hh = __float2bfloat16(kv);
        Kh[row * 40 + d] = hh;
        Kl[row * 40 + d] = __float2bfloat16(kv - __bfloat162float(hh));
        float vv = ok ? vp[row * 32 + d] : 0.f;
        hh = __float2bfloat16(vv);
        int pi = (row >> 1) * 80 + d * 2 + (row & 1);   // packed token pairs
        Vh[pi] = hh;
        Vl[pi] = __float2bfloat16(vv - __bfloat162float(hh));
    }
    for (int i = tid; i < 1183; i += 256) sBias[i] = bias_table[i * NHEAD + h];
    for (int cix = tid; cix < 224; cix += 256) {
        int v = 0;
        if (cix < NTOK) {
            int t = cix / 49, r = cix - t * 49, hh = r / 7, w = r - hh * 7;
            v = -(t * 169 + hh * 13 + w);
        }
        sCT[cix] = v;
    }
    __syncthreads();

    const uint32_t* Qh32 = (const uint32_t*)Qh;
    const uint32_t* Ql32 = (const uint32_t*)Ql;
    const uint32_t* Kh32 = (const uint32_t*)Kh;
    const uint32_t* Kl32 = (const uint32_t*)Kl;
    const uint32_t* Vh32 = (const uint32_t*)Vh;
    const uint32_t* Vl32 = (const uint32_t*)Vl;

    for (int strip = wid; strip < 14; strip += 8) {
        const int r0 = strip * 16;
        const int ra = r0 + qr, rb = ra + 8;
        int rtA = 591, rtB = 591;
        if (ra < NTOK) { int t = ra / 49, r = ra - t * 49, hh = r / 7, w = r - hh * 7;
                         rtA = t * 169 + hh * 13 + w + 591; }
        if (rb < NTOK) { int t = rb / 49, r = rb - t * 49, hh = r / 7, w = r - hh * 7;
                         rtB = t * 169 + hh * 13 + w + 591; }

        uint32_t qa[2][4], qe[2][4];
        #pragma unroll
        for (int kc = 0; kc < 2; kc++) {
            int b0 = (r0 + qr) * 20 + kc * 8 + qc;
            qa[kc][0] = Qh32[b0];       qa[kc][1] = Qh32[b0 + 160];
            qa[kc][2] = Qh32[b0 + 4];   qa[kc][3] = Qh32[b0 + 164];
            qe[kc][0] = Ql32[b0];       qe[kc][1] = Ql32[b0 + 160];
            qe[kc][2] = Ql32[b0 + 4];   qe[kc][3] = Ql32[b0 + 164];
        }

        float cc[28][4];
        #pragma unroll
        for (int nt = 0; nt < 28; nt++)
            #pragma unroll
            for (int k = 0; k < 4; k++) cc[nt][k] = 0.f;

        #pragma unroll
        for (int nt = 0; nt < 28; nt++) {
            int kb = (nt * 8 + qr) * 20 + qc;
            uint32_t h0 = Kh32[kb], h1 = Kh32[kb + 4], h2 = Kh32[kb + 8], h3 = Kh32[kb + 12];
            uint32_t l0 = Kl32[kb], l1 = Kl32[kb + 4], l2 = Kl32[kb + 8], l3 = Kl32[kb + 12];
            MMA16816(cc[nt], qa[0][0], qa[0][1], qa[0][2], qa[0][3], h0, h1);
            MMA16816(cc[nt], qa[1][0], qa[1][1], qa[1][2], qa[1][3], h2, h3);
            MMA16816(cc[nt], qe[0][0], qe[0][1], qe[0][2], qe[0][3], h0, h1);
            MMA16816(cc[nt], qe[1][0], qe[1][1], qe[1][2], qe[1][3], h2, h3);
            MMA16816(cc[nt], qa[0][0], qa[0][1], qa[0][2], qa[0][3], l0, l1);
            MMA16816(cc[nt], qa[1][0], qa[1][1], qa[1][2], qa[1][3], l2, l3);
        }

        // bias + mask + row max
        float mA = -1e30f, mB = -1e30f;
        #pragma unroll
        for (int nt = 0; nt < 28; nt++) {
            int c0 = nt * 8 + qc * 2;
            if (c0 < NTOK) {
                int ct = sCT[c0];
                cc[nt][0] += sBias[rtA + ct];
                cc[nt][2] += sBias[rtB + ct];
            } else { cc[nt][0] = -1e30f; cc[nt][2] = -1e30f; }
            if (c0 + 1 < NTOK) {
                int ct = sCT[c0 + 1];
                cc[nt][1] += sBias[rtA + ct];
                cc[nt][3] += sBias[rtB + ct];
            } else { cc[nt][1] = -1e30f; cc[nt][3] = -1e30f; }
            mA = fmaxf(mA, fmaxf(cc[nt][0], cc[nt][1]));
            mB = fmaxf(mB, fmaxf(cc[nt][2], cc[nt][3]));
        }
        mA = fmaxf(mA, __shfl_xor_sync(FULLMASK, mA, 1));
        mA = fmaxf(mA, __shfl_xor_sync(FULLMASK, mA, 2));
        mB = fmaxf(mB, __shfl_xor_sync(FULLMASK, mB, 1));
        mB = fmaxf(mB, __shfl_xor_sync(FULLMASK, mB, 2));

        float sumA = 0.f, sumB = 0.f;
        #pragma unroll
        for (int nt = 0; nt < 28; nt++) {
            cc[nt][0] = __expf(cc[nt][0] - mA); sumA += cc[nt][0];
            cc[nt][1] = __expf(cc[nt][1] - mA); sumA += cc[nt][1];
            cc[nt][2] = __expf(cc[nt][2] - mB); sumB += cc[nt][2];
            cc[nt][3] = __expf(cc[nt][3] - mB); sumB += cc[nt][3];
        }
        sumA += __shfl_xor_sync(FULLMASK, sumA, 1);
        sumA += __shfl_xor_sync(FULLMASK, sumA, 2);
        sumB += __shfl_xor_sync(FULLMASK, sumB, 1);
        sumB += __shfl_xor_sync(FULLMASK, sumB, 2);
        float iA = 1.f / sumA, iB = 1.f / sumB;

        // repack P (C-frag pairs -> A-frags), hi/lo
        uint32_t ph[14][4], pl[14][4];
        #pragma unroll
        for (int t = 0; t < 14; t++) {
            #pragma unroll
            for (int half = 0; half < 2; half++) {
                float x0 = cc[2 * t][2 * half], x1 = cc[2 * t][2 * half + 1];
                float y0 = cc[2 * t + 1][2 * half], y1 = cc[2 * t + 1][2 * half + 1];
                __nv_bfloat16 hx0 = __float2bfloat16(x0), hx1 = __float2bfloat16(x1);
                __nv_bfloat16 hy0 = __float2bfloat16(y0), hy1 = __float2bfloat16(y1);
                ph[t][half]     = pack_bf2(hx0, hx1);
                ph[t][half + 2] = pack_bf2(hy0, hy1);
                pl[t][half]     = pack_bf2(__float2bfloat16(x0 - __bfloat162float(hx0)),
                                           __float2bfloat16(x1 - __bfloat162float(hx1)));
                pl[t][half + 2] = pack_bf2(__float2bfloat16(y0 - __bfloat162float(hy0)),
                                           __float2bfloat16(y1 - __bfloat162float(hy1)));
            }
        }

        float oo[4][4];
        #pragma unroll
        for (int n2 = 0; n2 < 4; n2++)
            #pragma unroll
            for (int k = 0; k < 4; k++) oo[n2][k] = 0.f;

        #pragma unroll
        for (int t = 0; t < 14; t++) {
            #pragma unroll
            for (int n2 = 0; n2 < 4; n2++) {
                int vb = (t * 8 + qc) * 40 + n2 * 8 + qr;
                uint32_t bh0 = Vh32[vb], bh1 = Vh32[vb + 160];
                uint32_t bl0 = Vl32[vb], bl1 = Vl32[vb + 160];
                MMA16816(oo[n2], ph[t][0], ph[t][1], ph[t][2], ph[t][3], bh0, bh1);
                MMA16816(oo[n2], pl[t][0], pl[t][1], pl[t][2], pl[t][3], bh0, bh1);
                MMA16816(oo[n2], ph[t][0], ph[t][1], ph[t][2], ph[t][3], bl0, bl1);
            }
        }

        if (ra < NTOK) {
            size_t wb = ((size_t)(b_ * NTOK + ra)) * CDIM + h * HD;
            #pragma unroll
            for (int n2 = 0; n2 < 4; n2++) {
                int col = n2 * 8 + qc * 2;
                float x = oo[n2][0] * iA, y = oo[n2][1] * iA;
                __nv_bfloat16 hx = __float2bfloat16(x), hy = __float2bfloat16(y);
                ((uint32_t*)g_ath)[(wb + col) >> 1] = pack_bf2(hx, hy);
                ((uint32_t*)g_atl)[(wb + col) >> 1] =
                    pack_bf2(__float2bfloat16(x - __bfloat162float(hx)),
                             __float2bfloat16(y - __bfloat162float(hy)));
            }
        }
        if (rb < NTOK) {
            size_t wb = ((size_t)(b_ * NTOK + rb)) * CDIM + h * HD;
            #pragma unroll
            for (int n2 = 0; n2 < 4; n2++) {
                int col = n2 * 8 + qc * 2;
                float x = oo[n2][2] * iB, y = oo[n2][3] * iB;
                __nv_bfloat16 hx = __float2bfloat16(x), hy = __float2bfloat16(y);
                ((uint32_t*)g_ath)[(wb + col) >> 1] = pack_bf2(hx, hy);
                ((uint32_t*)g_atl)[(wb + col) >> 1] =
                    pack_bf2(__float2bfloat16(x - __bfloat162float(hx)),
                             __float2bfloat16(y - __bfloat162float(hy)));
            }
        }
    }
}

// ---------------------------------------------------------------------------
extern "C" void kernel_launch(void* const* d_in, const int* in_sizes, int n_in,
                              void* d_out, int out_size)
{
    const float* x      = (const float*)d_in[0];
    const float* qg     = (const float*)d_in[1];
    const float* kv_w   = (const float*)d_in[2];
    const float* kv_b   = (const float*)d_in[3];
    const float* proj_w = (const float*)d_in[4];
    const float* proj_b = (const float*)d_in[5];
    const float* btab   = (const float*)d_in[6];
    float* out = (float*)d_out;

    cudaFuncSetAttribute(attn_mma, cudaFuncAttributeMaxDynamicSharedMemorySize,
                         ATTN_SMEM_B);
    cudaFuncSetAttribute(gemm_mma<true>, cudaFuncAttributeMaxDynamicSharedMemorySize,
                         GEMM_SMEM);
    cudaFuncSetAttribute(gemm_mma<false>, cudaFuncAttributeMaxDynamicSharedMemorySize,
                         GEMM_SMEM);

    __nv_bfloat16 *xh, *xl, *kwh, *kwl, *pwh, *pwl, *ath, *atl;
    cudaGetSymbolAddress((void**)&xh,  g_xh);  cudaGetSymbolAddress((void**)&xl,  g_xl);
    cudaGetSymbolAddress((void**)&kwh, g_kwh); cudaGetSymbolAddress((void**)&kwl, g_kwl);
    cudaGetSymbolAddress((void**)&pwh, g_pwh); cudaGetSymbolAddress((void**)&pwl, g_pwl);
    cudaGetSymbolAddress((void**)&ath, g_ath); cudaGetSymbolAddress((void**)&atl, g_atl);

    int n4x = XELT / 4;
    split_kernel<<<(n4x + 255) / 256, 256>>>(x, xh, xl, n4x);
    int n4k = 2 * CDIM * CDIM / 4;
    split_kernel<<<(n4k + 255) / 256, 256>>>(kv_w, kwh, kwl, n4k);
    int n4p = CDIM * CDIM / 4;
    split_kernel<<<(n4p + 255) / 256, 256>>>(proj_w, pwh, pwl, n4p);

    dim3 gkv(2 * CDIM / 128, MROWS / 128);    // (8, 392)
    gemm_mma<true><<<gkv, 256, GEMM_SMEM>>>(xh, xl, kwh, kwl, kv_b, nullptr);

    dim3 gat(NHEAD, NWIN);                    // (16, 256)
    attn_mma<<<gat, 256, ATTN_SMEM_B>>>(qg, btab);

    dim3 gpj(CDIM / 128, MROWS / 128);        // (4, 392)
    gemm_mma<false><<<gpj, 256, GEMM_SMEM>>>(ath, atl, pwh, pwl, proj_b, out);
}

// round 10
// speedup vs baseline: 3.8257x; 1.1787x over previous
#include <cuda_runtime.h>
#include <cuda_bf16.h>
#include <cuda_fp16.h>
#include <cstdint>

#define FULLMASK 0xffffffffu

// Problem dims (static): B=4, B_dim=64 -> B_=256; N=196; C=512; H=16; hd=32
static constexpr int NWIN  = 256;
static constexpr int NTOK  = 196;
static constexpr int NHEAD = 16;
static constexpr int HD    = 32;
static constexpr int CDIM  = 512;
static constexpr int MROWS = NWIN * NTOK;        // 50176
static constexpr int XELT  = MROWS * CDIM;       // 25,690,112

// ---------------- static device scratch (no runtime allocation) -------------
__device__ float   g_K[XELT];                    // [b_,h,n,d] fp32
__device__ float   g_V[XELT];
__device__ __half  g_xh[XELT],  g_xl[XELT];      // x split (fp16 hi/lo)
__device__ __half  g_ath[XELT], g_atl[XELT];     // attn out split (fp16 hi/lo)
__device__ __half  g_kwh[2*CDIM*CDIM];           // kv_w rounded fp16
__device__ __half  g_pwh[CDIM*CDIM];             // proj_w rounded fp16

// ---------------- fp32 -> fp16 hi/lo splitter & rounder ---------------------
__global__ void split16_kernel(const float* __restrict__ src,
                               __half* __restrict__ hi,
                               __half* __restrict__ lo, int n4)
{
    int i = blockIdx.x * blockDim.x + threadIdx.x;
    if (i >= n4) return;
    float4 v = ((const float4*)src)[i];
    __half h0 = __float2half_rn(v.x), h1 = __float2half_rn(v.y);
    __half h2 = __float2half_rn(v.z), h3 = __float2half_rn(v.w);
    __half l0 = __float2half_rn(v.x - __half2float(h0));
    __half l1 = __float2half_rn(v.y - __half2float(h1));
    __half l2 = __float2half_rn(v.z - __half2float(h2));
    __half l3 = __float2half_rn(v.w - __half2float(h3));
    __half2* H = (__half2*)hi;
    __half2* L = (__half2*)lo;
    H[2 * i]     = __halves2half2(h0, h1);
    H[2 * i + 1] = __halves2half2(h2, h3);
    L[2 * i]     = __halves2half2(l0, l1);
    L[2 * i + 1] = __halves2half2(l2, l3);
}

__global__ void round16_kernel(const float* __restrict__ src,
                               __half* __restrict__ dst, int n4)
{
    int i = blockIdx.x * blockDim.x + threadIdx.x;
    if (i >= n4) return;
    float4 v = ((const float4*)src)[i];
    __half2* D = (__half2*)dst;
    D[2 * i]     = __halves2half2(__float2half_rn(v.x), __float2half_rn(v.y));
    D[2 * i + 1] = __halves2half2(__float2half_rn(v.z), __float2half_rn(v.w));
}

// ---------------- mma plumbing ----------------------------------------------
#define MMA16816(cc, a0, a1, a2, a3, b0, b1)                                    \
    asm volatile("mma.sync.aligned.m16n8k16.row.col.f32.bf16.bf16.f32 "         \
                 "{%0,%1,%2,%3}, {%4,%5,%6,%7}, {%8,%9}, {%0,%1,%2,%3};"        \
                 : "+f"((cc)[0]), "+f"((cc)[1]), "+f"((cc)[2]), "+f"((cc)[3])   \
                 : "r"(a0), "r"(a1), "r"(a2), "r"(a3), "r"(b0), "r"(b1))

#define MMAF16(cc, a0, a1, a2, a3, b0, b1)                                      \
    asm volatile("mma.sync.aligned.m16n8k16.row.col.f32.f16.f16.f32 "           \
                 "{%0,%1,%2,%3}, {%4,%5,%6,%7}, {%8,%9}, {%0,%1,%2,%3};"        \
                 : "+f"((cc)[0]), "+f"((cc)[1]), "+f"((cc)[2]), "+f"((cc)[3])   \
                 : "r"(a0), "r"(a1), "r"(a2), "r"(a3), "r"(b0), "r"(b1))

#define LDSM_X4(r0, r1, r2, r3, addr)                                           \
    asm volatile("ldmatrix.sync.aligned.m8n8.x4.shared.b16 {%0,%1,%2,%3}, [%4];"\
        : "=r"(r0), "=r"(r1), "=r"(r2), "=r"(r3) : "r"(addr))

#define CP16(saddr, gptr)                                                       \
    asm volatile("cp.async.cg.shared.global [%0], [%1], 16;"                    \
        :: "r"(saddr), "l"(gptr) : "memory")

__device__ __forceinline__ uint32_t smem_u32(const void* p) {
    uint32_t a;
    asm("{ .reg .u64 t; cvta.to.shared.u64 t, %1; cvt.u32.u64 %0, t; }"
        : "=r"(a) : "l"(p));
    return a;
}

__device__ __forceinline__ uint32_t pack_bf2(__nv_bfloat16 a, __nv_bfloat16 b) {
    uint16_t ua = *(uint16_t*)&a, ub = *(uint16_t*)&b;
    return ((uint32_t)ub << 16) | ua;
}
__device__ __forceinline__ uint32_t pack_h2(__half a, __half b) {
    uint16_t ua = *(uint16_t*)&a, ub = *(uint16_t*)&b;
    return ((uint32_t)ub << 16) | ua;
}

// ---------------- fp16 2-pass GEMM (cp.async 3-stage + ldmatrix) -------------
// C = A @ W^T + bias, A split (Ah+Al = exact), W rounded fp16.
// CTA tile 128x128, K-chunk 32. Tiles per stage: Ah, Al, Wh.
static constexpr int SROW    = 20;
static constexpr int TILE_W  = 128 * SROW;           // 2560 words
static constexpr int TILE_B  = TILE_W * 4;           // 10240 bytes
static constexpr int STAGE_B = 3 * TILE_B;           // 30720 bytes
static constexpr int GEMM_SMEM = 512 + 3 * STAGE_B;  // 92672 bytes

template <bool KV>
__global__ __launch_bounds__(256, 2)
void gemm_mma(const __half* __restrict__ Ah, const __half* __restrict__ Al,
              const __half* __restrict__ Wh,
              const float* __restrict__ bias, float* __restrict__ out)
{
    extern __shared__ char smg[];
    float* bias_s = (float*)smg;
    const uint32_t swb = smem_u32(smg + 512);

    const int tid = threadIdx.x;
    const int wid = tid >> 5, lane = tid & 31;
    const int qr = lane >> 2, qc = lane & 3;
    const int n0 = blockIdx.x * 128, m0 = blockIdx.y * 128;
    const int mbase = (wid >> 2) * 64, nbase = (wid & 3) * 32;

    if (tid < 128) bias_s[tid] = bias[n0 + tid];

    const uint4* A4h = (const uint4*)Ah;
    const uint4* A4l = (const uint4*)Al;
    const uint4* W4h = (const uint4*)Wh;

    const int r0i = (tid * 2) >> 2, c40 = (tid * 2) & 3;
    const int r1i = (tid * 2 + 1) >> 2, c41 = (tid * 2 + 1) & 3;

    auto issue_stage = [&](int kc, int s) {
        uint32_t sb = swb + s * STAGE_B;
        {
            uint32_t so = (uint32_t)(r0i * SROW + c40 * 4) * 4;
            size_t ga = (size_t)(m0 + r0i) * 64 + kc * 4 + c40;
            size_t gw = (size_t)(n0 + r0i) * 64 + kc * 4 + c40;
            CP16(sb + so,              A4h + ga);
            CP16(sb + TILE_B + so,     A4l + ga);
            CP16(sb + 2 * TILE_B + so, W4h + gw);
        }
        {
            uint32_t so = (uint32_t)(r1i * SROW + c41 * 4) * 4;
            size_t ga = (size_t)(m0 + r1i) * 64 + kc * 4 + c41;
            size_t gw = (size_t)(n0 + r1i) * 64 + kc * 4 + c41;
            CP16(sb + so,              A4h + ga);
            CP16(sb + TILE_B + so,     A4l + ga);
            CP16(sb + 2 * TILE_B + so, W4h + gw);
        }
        asm volatile("cp.async.commit_group;" ::: "memory");
    };

    float c[4][4][4];
    #pragma unroll
    for (int mt = 0; mt < 4; mt++)
        #pragma unroll
        for (int nt = 0; nt < 4; nt++)
            #pragma unroll
            for (int k = 0; k < 4; k++) c[mt][nt][k] = 0.f;

    issue_stage(0, 0);
    issue_stage(1, 1);
    issue_stage(2, 2);

    const int aRow = lane & 15, aKh = lane >> 4;
    const int wSub = lane >> 3;
    const int wRow = ((wSub >> 1) * 8) + (lane & 7), wKh = wSub & 1;

    int s = 0;
    for (int kc = 0; kc < 16; kc++) {
        if (kc < 14)       asm volatile("cp.async.wait_group 2;" ::: "memory");
        else if (kc == 14) asm volatile("cp.async.wait_group 1;" ::: "memory");
        else               asm volatile("cp.async.wait_group 0;" ::: "memory");
        __syncthreads();

        const uint32_t tb = swb + s * STAGE_B;
        #pragma unroll
        for (int ks = 0; ks < 2; ks++) {
            uint32_t bh[4][2];
            #pragma unroll
            for (int np = 0; np < 2; np++) {
                uint32_t wa = tb + 2 * TILE_B +
                    (uint32_t)(((nbase + np * 16 + wRow) * SROW + ks * 8 + wKh * 4) * 4);
                LDSM_X4(bh[np*2][0], bh[np*2][1], bh[np*2+1][0], bh[np*2+1][1], wa);
            }
            #pragma unroll
            for (int mt = 0; mt < 4; mt++) {
                uint32_t aa = tb +
                    (uint32_t)(((mbase + mt * 16 + aRow) * SROW + ks * 8 + aKh * 4) * 4);
                uint32_t a0, a1, a2, a3, e0, e1, e2, e3;
                LDSM_X4(a0, a1, a2, a3, aa);
                LDSM_X4(e0, e1, e2, e3, aa + TILE_B);
                #pragma unroll
                for (int nt = 0; nt < 4; nt++)
                    MMAF16(c[mt][nt], a0, a1, a2, a3, bh[nt][0], bh[nt][1]);
                #pragma unroll
                for (int nt = 0; nt < 4; nt++)
                    MMAF16(c[mt][nt], e0, e1, e2, e3, bh[nt][0], bh[nt][1]);
            }
        }
        __syncthreads();
        if (kc + 3 < 16) issue_stage(kc + 3, s);
        s = (s == 2) ? 0 : s + 1;
    }

    // epilogue
    #pragma unroll
    for (int mt = 0; mt < 4; mt++) {
        #pragma unroll
        for (int half = 0; half < 2; half++) {
            int m = m0 + mbase + mt * 16 + qr + 8 * half;
            int b_ = m / NTOK, n = m - b_ * NTOK;
            #pragma unroll
            for (int nt = 0; nt < 4; nt++) {
                int col = n0 + nbase + nt * 8 + qc * 2;
                float2 v;
                v.x = c[mt][nt][2 * half]     + bias_s[col - n0];
                v.y = c[mt][nt][2 * half + 1] + bias_s[col - n0 + 1];
                if (KV) {
                    float* dst = (col < CDIM) ? g_K : g_V;
                    int cm = col & (CDIM - 1);
                    int h = cm >> 5, d = cm & 31;
                    *(float2*)(dst + ((size_t)((b_ * NHEAD + h) * NTOK + n)) * HD + d) = v;
                } else {
                    *(float2*)(out + (size_t)m * CDIM + col) = v;
                }
            }
        }
    }
}

// ---------------- mma.sync attention (bf16x3 internally) --------------------
static constexpr int ATTN_SMEM_B = 28288 * 4;

__global__ __launch_bounds__(256, 1)
void attn_mma(const float* __restrict__ q_global,
              const float* __restrict__ bias_table)
{
    extern __shared__ float sm[];
    __nv_bfloat16* Qh = (__nv_bfloat16*)(sm);
    __nv_bfloat16* Ql = (__nv_bfloat16*)(sm + 4480);
    __nv_bfloat16* Kh = (__nv_bfloat16*)(sm + 8960);
    __nv_bfloat16* Kl = (__nv_bfloat16*)(sm + 13440);
    __nv_bfloat16* Vh = (__nv_bfloat16*)(sm + 17920);
    __nv_bfloat16* Vl = (__nv_bfloat16*)(sm + 22400);
    float* sBias = sm + 26880;
    int*   sCT   = (int*)(sm + 28064);

    const int h = blockIdx.x, b_ = blockIdx.y;
    const int tid = threadIdx.x, lane = tid & 31, wid = tid >> 5;
    const int qr = lane >> 2, qc = lane & 3;

    const float* qp = q_global + (size_t)(((b_ >> 6) * NHEAD + h) * NTOK) * HD;
    const float* kp = g_K + (size_t)((b_ * NHEAD + h) * NTOK) * HD;
    const float* vp = g_V + (size_t)((b_ * NHEAD + h) * NTOK) * HD;

    for (int i = tid; i < 224 * 32; i += 256) {
        int row = i >> 5, d = i & 31;
        bool ok = row < NTOK;
        float qv = ok ? qp[row * 32 + d] * 0.17677669529663687f : 0.f;
        __nv_bfloat16 hh = __float2bfloat16(qv);
        Qh[row * 40 + d] = hh;
        Ql[row * 40 + d] = __float2bfloat16(qv - __bfloat162float(hh));
        float kv = ok ? kp[row * 32 + d] : 0.f;
        hh = __float2bfloat16(kv);
        Kh[row * 40 + d] = hh;
        Kl[row * 40 + d] = __float2bfloat16(kv - __bfloat162float(hh));
        float vv = ok ? vp[row * 32 + d] : 0.f;
        hh = __float2bfloat16(vv);
        int pi = (row >> 1) * 80 + d * 2 + (row & 1);
        Vh[pi] = hh;
        Vl[pi] = __float2bfloat16(vv - __bfloat162float(hh));
    }
    for (int i = tid; i < 1183; i += 256) sBias[i] = bias_table[i * NHEAD + h];
    for (int cix = tid; cix < 224; cix += 256) {
        int v = 0;
        if (cix < NTOK) {
            int t = cix / 49, r = cix - t * 49, hh = r / 7, w = r - hh * 7;
            v = -(t * 169 + hh * 13 + w);
        }
        sCT[cix] = v;
    }
    __syncthreads();

    const uint32_t* Qh32 = (const uint32_t*)Qh;
    const uint32_t* Ql32 = (const uint32_t*)Ql;
    const uint32_t* Kh32 = (const uint32_t*)Kh;
    const uint32_t* Kl32 = (const uint32_t*)Kl;
    const uint32_t* Vh32 = (const uint32_t*)Vh;
    const uint32_t* Vl32 = (const uint32_t*)Vl;

    for (int strip = wid; strip < 14; strip += 8) {
        const int r0 = strip * 16;
        const int ra = r0 + qr, rb = ra + 8;
        int rtA = 591, rtB = 591;
        if (ra < NTOK) { int t = ra / 49, r = ra - t * 49, hh = r / 7, w = r - hh * 7;
                         rtA = t * 169 + hh * 13 + w + 591; }
        if (rb < NTOK) { int t = rb / 49, r = rb - t * 49, hh = r / 7, w = r - hh * 7;
                         rtB = t * 169 + hh * 13 + w + 591; }

        uint32_t qa[2][4], qe[2][4];
        #pragma unroll
        for (int kc = 0; kc < 2; kc++) {
            int b0 = (r0 + qr) * 20 + kc * 8 + qc;
            qa[kc][0] = Qh32[b0];       qa[kc][1] = Qh32[b0 + 160];
            qa[kc][2] = Qh32[b0 + 4];   qa[kc][3] = Qh32[b0 + 164];
            qe[kc][0] = Ql32[b0];       qe[kc][1] = Ql32[b0 + 160];
            qe[kc][2] = Ql32[b0 + 4];   qe[kc][3] = Ql32[b0 + 164];
        }

        float cc[28][4];
        #pragma unroll
        for (int nt = 0; nt < 28; nt++)
            #pragma unroll
            for (int k = 0; k < 4; k++) cc[nt][k] = 0.f;

        #pragma unroll
        for (int nt = 0; nt < 28; nt++) {
            int kb = (nt * 8 + qr) * 20 + qc;
            uint32_t h0 = Kh32[kb], h1 = Kh32[kb + 4], h2 = Kh32[kb + 8], h3 = Kh32[kb + 12];
            uint32_t l0 = Kl32[kb], l1 = Kl32[kb + 4], l2 = Kl32[kb + 8], l3 = Kl32[kb + 12];
            MMA16816(cc[nt], qa[0][0], qa[0][1], qa[0][2], qa[0][3], h0, h1);
            MMA16816(cc[nt], qa[1][0], qa[1][1], qa[1][2], qa[1][3], h2, h3);
            MMA16816(cc[nt], qe[0][0], qe[0][1], qe[0][2], qe[0][3], h0, h1);
            MMA16816(cc[nt], qe[1][0], qe[1][1], qe[1][2], qe[1][3], h2, h3);
            MMA16816(cc[nt], qa[0][0], qa[0][1], qa[0][2], qa[0][3], l0, l1);
            MMA16816(cc[nt], qa[1][0], qa[1][1], qa[1][2], qa[1][3], l2, l3);
        }

        float mA = -1e30f, mB = -1e30f;
        #pragma unroll
        for (int nt = 0; nt < 28; nt++) {
            int c0 = nt * 8 + qc * 2;
            if (c0 < NTOK) {
                int ct = sCT[c0];
                cc[nt][0] += sBias[rtA + ct];
                cc[nt][2] += sBias[rtB + ct];
            } else { cc[nt][0] = -1e30f; cc[nt][2] = -1e30f; }
            if (c0 + 1 < NTOK) {
                int ct = sCT[c0 + 1];
                cc[nt][1] += sBias[rtA + ct];
                cc[nt][3] += sBias[rtB + ct];
            } else { cc[nt][1] = -1e30f; cc[nt][3] = -1e30f; }
            mA = fmaxf(mA, fmaxf(cc[nt][0], cc[nt][1]));
            mB = fmaxf(mB, fmaxf(cc[nt][2], cc[nt][3]));
        }
        mA = fmaxf(mA, __shfl_xor_sync(FULLMASK, mA, 1));
        mA = fmaxf(mA, __shfl_xor_sync(FULLMASK, mA, 2));
        mB = fmaxf(mB, __shfl_xor_sync(FULLMASK, mB, 1));
        mB = fmaxf(mB, __shfl_xor_sync(FULLMASK, mB, 2));

        float sumA = 0.f, sumB = 0.f;
        #pragma unroll
        for (int nt = 0; nt < 28; nt++) {
            cc[nt][0] = __expf(cc[nt][0] - mA); sumA += cc[nt][0];
            cc[nt][1] = __expf(cc[nt][1] - mA); sumA += cc[nt][1];
            cc[nt][2] = __expf(cc[nt][2] - mB); sumB += cc[nt][2];
            cc[nt][3] = __expf(cc[nt][3] - mB); sumB += cc[nt][3];
        }
        sumA += __shfl_xor_sync(FULLMASK, sumA, 1);
        sumA += __shfl_xor_sync(FULLMASK, sumA, 2);
        sumB += __shfl_xor_sync(FULLMASK, sumB, 1);
        sumB += __shfl_xor_sync(FULLMASK, sumB, 2);
        float iA = 1.f / sumA, iB = 1.f / sumB;

        uint32_t ph[14][4], pl[14][4];
        #pragma unroll
        for (int t = 0; t < 14; t++) {
            #pragma unroll
            for (int half = 0; half < 2; half++) {
                float x0 = cc[2 * t][2 * half], x1 = cc[2 * t][2 * half + 1];
                float y0 = cc[2 * t + 1][2 * half], y1 = cc[2 * t + 1][2 * half + 1];
                __nv_bfloat16 hx0 = __float2bfloat16(x0), hx1 = __float2bfloat16(x1);
                __nv_bfloat16 hy0 = __float2bfloat16(y0), hy1 = __float2bfloat16(y1);
                ph[t][half]     = pack_bf2(hx0, hx1);
                ph[t][half + 2] = pack_bf2(hy0, hy1);
                pl[t][half]     = pack_bf2(__float2bfloat16(x0 - __bfloat162float(hx0)),
                                           __float2bfloat16(x1 - __bfloat162float(hx1)));
                pl[t][half + 2] = pack_bf2(__float2bfloat16(y0 - __bfloat162float(hy0)),
                                           __float2bfloat16(y1 - __bfloat162float(hy1)));
            }
        }

        float oo[4][4];
        #pragma unroll
        for (int n2 = 0; n2 < 4; n2++)
            #pragma unroll
            for (int k = 0; k < 4; k++) oo[n2][k] = 0.f;

        #pragma unroll
        for (int t = 0; t < 14; t++) {
            #pragma unroll
            for (int n2 = 0; n2 < 4; n2++) {
                int vb = (t * 8 + qc) * 40 + n2 * 8 + qr;
                uint32_t bh0 = Vh32[vb], bh1 = Vh32[vb + 160];
                uint32_t bl0 = Vl32[vb], bl1 = Vl32[vb + 160];
                MMA16816(oo[n2], ph[t][0], ph[t][1], ph[t][2], ph[t][3], bh0, bh1);
                MMA16816(oo[n2], pl[t][0], pl[t][1], pl[t][2], pl[t][3], bh0, bh1);
                MMA16816(oo[n2], ph[t][0], ph[t][1], ph[t][2], ph[t][3], bl0, bl1);
            }
        }

        if (ra < NTOK) {
            size_t wb = ((size_t)(b_ * NTOK + ra)) * CDIM + h * HD;
            #pragma unroll
            for (int n2 = 0; n2 < 4; n2++) {
                int col = n2 * 8 + qc * 2;
                float x = oo[n2][0] * iA, y = oo[n2][1] * iA;
                __half hx = __float2half_rn(x), hy = __float2half_rn(y);
                ((uint32_t*)g_ath)[(wb + col) >> 1] = pack_h2(hx, hy);
                ((uint32_t*)g_atl)[(wb + col) >> 1] =
                    pack_h2(__float2half_rn(x - __half2float(hx)),
                            __float2half_rn(y - __half2float(hy)));
            }
        }
        if (rb < NTOK) {
            size_t wb = ((size_t)(b_ * NTOK + rb)) * CDIM + h * HD;
            #pragma unroll
            for (int n2 = 0; n2 < 4; n2++) {
                int col = n2 * 8 + qc * 2;
                float x = oo[n2][2] * iB, y = oo[n2][3] * iB;
                __half hx = __float2half_rn(x), hy = __float2half_rn(y);
                ((uint32_t*)g_ath)[(wb + col) >> 1] = pack_h2(hx, hy);
                ((uint32_t*)g_atl)[(wb + col) >> 1] =
                    pack_h2(__float2half_rn(x - __half2float(hx)),
                            __float2half_rn(y - __half2float(hy)));
            }
        }
    }
}

// ---------------------------------------------------------------------------
extern "C" void kernel_launch(void* const* d_in, const int* in_sizes, int n_in,
                              void* d_out, int out_size)
{
    const float* x      = (const float*)d_in[0];
    const float* qg     = (const float*)d_in[1];
    const float* kv_w   = (const float*)d_in[2];
    const float* kv_b   = (const float*)d_in[3];
    const float* proj_w = (const float*)d_in[4];
    const float* proj_b = (const float*)d_in[5];
    const float* btab   = (const float*)d_in[6];
    float* out = (float*)d_out;

    cudaFuncSetAttribute(attn_mma, cudaFuncAttributeMaxDynamicSharedMemorySize,
                         ATTN_SMEM_B);
    cudaFuncSetAttribute(gemm_mma<true>, cudaFuncAttributeMaxDynamicSharedMemorySize,
                         GEMM_SMEM);
    cudaFuncSetAttribute(gemm_mma<false>, cudaFuncAttributeMaxDynamicSharedMemorySize,
                         GEMM_SMEM);

    __half *xh, *xl, *kwh, *pwh, *ath, *atl;
    cudaGetSymbolAddress((void**)&xh,  g_xh);  cudaGetSymbolAddress((void**)&xl,  g_xl);
    cudaGetSymbolAddress((void**)&kwh, g_kwh); cudaGetSymbolAddress((void**)&pwh, g_pwh);
    cudaGetSymbolAddress((void**)&ath, g_ath); cudaGetSymbolAddress((void**)&atl, g_atl);

    int n4x = XELT / 4;
    split16_kernel<<<(n4x + 255) / 256, 256>>>(x, xh, xl, n4x);
    int n4k = 2 * CDIM * CDIM / 4;
    round16_kernel<<<(n4k + 255) / 256, 256>>>(kv_w, kwh, n4k);
    int n4p = CDIM * CDIM / 4;
    round16_kernel<<<(n4p + 255) / 256, 256>>>(proj_w, pwh, n4p);

    dim3 gkv(2 * CDIM / 128, MROWS / 128);    // (8, 392)
    gemm_mma<true><<<gkv, 256, GEMM_SMEM>>>(xh, xl, kwh, kv_b, nullptr);

    dim3 gat(NHEAD, NWIN);                    // (16, 256)
    attn_mma<<<gat, 256, ATTN_SMEM_B>>>(qg, btab);

    dim3 gpj(CDIM / 128, MROWS / 128);        // (4, 392)
    gemm_mma<false><<<gpj, 256, GEMM_SMEM>>>(ath, atl, pwh, proj_b, out);
}

// round 12
// speedup vs baseline: 5.2790x; 1.3799x over previous
#include <cuda_runtime.h>
#include <cuda_bf16.h>
#include <cuda_fp16.h>
#include <cstdint>

#define FULLMASK 0xffffffffu

// Problem dims (static): B=4, B_dim=64 -> B_=256; N=196; C=512; H=16; hd=32
static constexpr int NWIN  = 256;
static constexpr int NTOK  = 196;
static constexpr int NHEAD = 16;
static constexpr int HD    = 32;
static constexpr int CDIM  = 512;
static constexpr int MROWS = NWIN * NTOK;        // 50176
static constexpr int XELT  = MROWS * CDIM;       // 25,690,112

// ---------------- static device scratch (no runtime allocation) -------------
__device__ float   g_K[XELT];                    // [b_,h,n,d] fp32
__device__ float   g_V[XELT];
__device__ __half  g_xh[XELT];                   // x rounded fp16
__device__ __half  g_ath[XELT];                  // attn out rounded fp16
__device__ __half  g_kwh[2*CDIM*CDIM];           // kv_w rounded fp16
__device__ __half  g_pwh[CDIM*CDIM];             // proj_w rounded fp16

// ---------------- fp32 -> fp16 rounder ---------------------------------------
__global__ void round16_kernel(const float* __restrict__ src,
                               __half* __restrict__ dst, int n4)
{
    int i = blockIdx.x * blockDim.x + threadIdx.x;
    if (i >= n4) return;
    float4 v = ((const float4*)src)[i];
    __half2* D = (__half2*)dst;
    D[2 * i]     = __halves2half2(__float2half_rn(v.x), __float2half_rn(v.y));
    D[2 * i + 1] = __halves2half2(__float2half_rn(v.z), __float2half_rn(v.w));
}

// ---------------- mma plumbing ----------------------------------------------
#define MMA16816(cc, a0, a1, a2, a3, b0, b1)                                    \
    asm volatile("mma.sync.aligned.m16n8k16.row.col.f32.bf16.bf16.f32 "         \
                 "{%0,%1,%2,%3}, {%4,%5,%6,%7}, {%8,%9}, {%0,%1,%2,%3};"        \
                 : "+f"((cc)[0]), "+f"((cc)[1]), "+f"((cc)[2]), "+f"((cc)[3])   \
                 : "r"(a0), "r"(a1), "r"(a2), "r"(a3), "r"(b0), "r"(b1))

#define MMAF16(cc, a0, a1, a2, a3, b0, b1)                                      \
    asm volatile("mma.sync.aligned.m16n8k16.row.col.f32.f16.f16.f32 "           \
                 "{%0,%1,%2,%3}, {%4,%5,%6,%7}, {%8,%9}, {%0,%1,%2,%3};"        \
                 : "+f"((cc)[0]), "+f"((cc)[1]), "+f"((cc)[2]), "+f"((cc)[3])   \
                 : "r"(a0), "r"(a1), "r"(a2), "r"(a3), "r"(b0), "r"(b1))

#define LDSM_X4(r0, r1, r2, r3, addr)                                           \
    asm volatile("ldmatrix.sync.aligned.m8n8.x4.shared.b16 {%0,%1,%2,%3}, [%4];"\
        : "=r"(r0), "=r"(r1), "=r"(r2), "=r"(r3) : "r"(addr))

#define CP16(saddr, gptr)                                                       \
    asm volatile("cp.async.cg.shared.global [%0], [%1], 16;"                    \
        :: "r"(saddr), "l"(gptr) : "memory")

__device__ __forceinline__ uint32_t smem_u32(const void* p) {
    uint32_t a;
    asm("{ .reg .u64 t; cvta.to.shared.u64 t, %1; cvt.u32.u64 %0, t; }"
        : "=r"(a) : "l"(p));
    return a;
}

__device__ __forceinline__ uint32_t pack_bf2(__nv_bfloat16 a, __nv_bfloat16 b) {
    uint16_t ua = *(uint16_t*)&a, ub = *(uint16_t*)&b;
    return ((uint32_t)ub << 16) | ua;
}
__device__ __forceinline__ uint32_t pack_h2(__half a, __half b) {
    uint16_t ua = *(uint16_t*)&a, ub = *(uint16_t*)&b;
    return ((uint32_t)ub << 16) | ua;
}

// ---------------- fp16 1-pass GEMM (K-chunk 64, 3-buffer, 1 sync/chunk) ------
// C = A @ W^T + bias. A and W both rounded fp16.
// Smem tile: 128 rows x (32 data + 4 pad) words. Buffers hold {A, W}.
static constexpr int SROW    = 36;                    // words per row
static constexpr int TILE_B  = 128 * SROW * 4;        // 18432 bytes
static constexpr int STAGE_B = 2 * TILE_B;            // 36864 bytes
static constexpr int GEMM_SMEM = 512 + 3 * STAGE_B;   // 111104 bytes

template <bool KV>
__global__ __launch_bounds__(256, 2)
void gemm_mma(const __half* __restrict__ Ah, const __half* __restrict__ Wh,
              const float* __restrict__ bias, float* __restrict__ out)
{
    extern __shared__ char smg[];
    float* bias_s = (float*)smg;
    const uint32_t swb = smem_u32(smg + 512);

    const int tid = threadIdx.x;
    const int wid = tid >> 5, lane = tid & 31;
    const int qr = lane >> 2, qc = lane & 3;
    const int n0 = blockIdx.x * 128, m0 = blockIdx.y * 128;
    const int mbase = (wid >> 2) * 64, nbase = (wid & 3) * 32;

    if (tid < 128) bias_s[tid] = bias[n0 + tid];

    const uint4* A4 = (const uint4*)Ah;
    const uint4* W4 = (const uint4*)Wh;

    // fill one buffer: per tile 128 rows x 8 uint4; 4 chunks per thread per tile
    auto issue_stage = [&](int kc, int s) {       // kc in K64 units
        uint32_t sb = swb + s * STAGE_B;
        #pragma unroll
        for (int it = 0; it < 4; it++) {
            int idx = tid + it * 256;
            int row = idx >> 3, c8 = idx & 7;
            uint32_t so = (uint32_t)(row * SROW + c8 * 4) * 4;
            size_t ga = (size_t)(m0 + row) * 64 + kc * 8 + c8;
            size_t gw = (size_t)(n0 + row) * 64 + kc * 8 + c8;
            CP16(sb + so,          A4 + ga);
            CP16(sb + TILE_B + so, W4 + gw);
        }
        asm volatile("cp.async.commit_group;" ::: "memory");
    };

    float c[4][4][4];
    #pragma unroll
    for (int mt = 0; mt < 4; mt++)
        #pragma unroll
        for (int nt = 0; nt < 4; nt++)
            #pragma unroll
            for (int k = 0; k < 4; k++) c[mt][nt][k] = 0.f;

    issue_stage(0, 0);
    issue_stage(1, 1);

    const int aRow = lane & 15, aKh = lane >> 4;
    const int wSub = lane >> 3;
    const int wRow = ((wSub >> 1) * 8) + (lane & 7), wKh = wSub & 1;

    for (int kc = 0; kc < 8; kc++) {              // 8 chunks of K=64
        if (kc < 7) asm volatile("cp.async.wait_group 1;" ::: "memory");
        else        asm volatile("cp.async.wait_group 0;" ::: "memory");
        __syncthreads();
        // issue next chunk into the buffer computed last iteration (drained by
        // the sync above) — single sync per chunk.
        if (kc + 2 < 8) issue_stage(kc + 2, (kc + 2) % 3);

        const uint32_t tb = swb + (kc % 3) * STAGE_B;
        #pragma unroll
        for (int ks = 0; ks < 4; ks++) {          // four k16 steps
            uint32_t bh[4][2];
            #pragma unroll
            for (int np = 0; np < 2; np++) {
                uint32_t wa = tb + TILE_B +
                    (uint32_t)(((nbase + np * 16 + wRow) * SROW + ks * 8 + wKh * 4) * 4);
                LDSM_X4(bh[np*2][0], bh[np*2][1], bh[np*2+1][0], bh[np*2+1][1], wa);
            }
            #pragma unroll
            for (int mt = 0; mt < 4; mt++) {
                uint32_t aa = tb +
                    (uint32_t)(((mbase + mt * 16 + aRow) * SROW + ks * 8 + aKh * 4) * 4);
                uint32_t a0, a1, a2, a3;
                LDSM_X4(a0, a1, a2, a3, aa);
                #pragma unroll
                for (int nt = 0; nt < 4; nt++)
                    MMAF16(c[mt][nt], a0, a1, a2, a3, bh[nt][0], bh[nt][1]);
            }
        }
    }

    // epilogue
    #pragma unroll
    for (int mt = 0; mt < 4; mt++) {
        #pragma unroll
        for (int half = 0; half < 2; half++) {
            int m = m0 + mbase + mt * 16 + qr + 8 * half;
            int b_ = m / NTOK, n = m - b_ * NTOK;
            #pragma unroll
            for (int nt = 0; nt < 4; nt++) {
                int col = n0 + nbase + nt * 8 + qc * 2;
                float2 v;
                v.x = c[mt][nt][2 * half]     + bias_s[col - n0];
                v.y = c[mt][nt][2 * half + 1] + bias_s[col - n0 + 1];
                if (KV) {
                    float* dst = (col < CDIM) ? g_K : g_V;
                    int cm = col & (CDIM - 1);
                    int h = cm >> 5, d = cm & 31;
                    *(float2*)(dst + ((size_t)((b_ * NHEAD + h) * NTOK + n)) * HD + d) = v;
                } else {
                    *(float2*)(out + (size_t)m * CDIM + col) = v;
                }
            }
        }
    }
}

// ---------------- mma.sync attention (bf16x3 internally) --------------------
static constexpr int ATTN_SMEM_B = 28288 * 4;

__global__ __launch_bounds__(256, 1)
void attn_mma(const float* __restrict__ q_global,
              const float* __restrict__ bias_table)
{
    extern __shared__ float sm[];
    __nv_bfloat16* Qh = (__nv_bfloat16*)(sm);
    __nv_bfloat16* Ql = (__nv_bfloat16*)(sm + 4480);
    __nv_bfloat16* Kh = (__nv_bfloat16*)(sm + 8960);
    __nv_bfloat16* Kl = (__nv_bfloat16*)(sm + 13440);
    __nv_bfloat16* Vh = (__nv_bfloat16*)(sm + 17920);
    __nv_bfloat16* Vl = (__nv_bfloat16*)(sm + 22400);
    float* sBias = sm + 26880;
    int*   sCT   = (int*)(sm + 28064);

    const int h = blockIdx.x, b_ = blockIdx.y;
    const int tid = threadIdx.x, lane = tid & 31, wid = tid >> 5;
    const int qr = lane >> 2, qc = lane & 3;

    const float* qp = q_global + (size_t)(((b_ >> 6) * NHEAD + h) * NTOK) * HD;
    const float* kp = g_K + (size_t)((b_ * NHEAD + h) * NTOK) * HD;
    const float* vp = g_V + (size_t)((b_ * NHEAD + h) * NTOK) * HD;

    for (int i = tid; i < 224 * 32; i += 256) {
        int row = i >> 5, d = i & 31;
        bool ok = row < NTOK;
        float qv = ok ? qp[row * 32 + d] * 0.17677669529663687f : 0.f;
        __nv_bfloat16 hh = __float2bfloat16(qv);
        Qh[row * 40 + d] = hh;
        Ql[row * 40 + d] = __float2bfloat16(qv - __bfloat162float(hh));
        float kv = ok ? kp[row * 32 + d] : 0.f;
        hh = __float2bfloat16(kv);
        Kh[row * 40 + d] = hh;
        Kl[row * 40 + d] = __float2bfloat16(kv - __bfloat162float(hh));
        float vv = ok ? vp[row * 32 + d] : 0.f;
        hh = __float2bfloat16(vv);
        int pi = (row >> 1) * 80 + d * 2 + (row & 1);
        Vh[pi] = hh;
        Vl[pi] = __float2bfloat16(vv - __bfloat162float(hh));
    }
    for (int i = tid; i < 1183; i += 256) sBias[i] = bias_table[i * NHEAD + h];
    for (int cix = tid; cix < 224; cix += 256) {
        int v = 0;
        if (cix < NTOK) {
            int t = cix / 49, r = cix - t * 49, hh = r / 7, w = r - hh * 7;
            v = -(t * 169 + hh * 13 + w);
        }
        sCT[cix] = v;
    }
    __syncthreads();

    const uint32_t* Qh32 = (const uint32_t*)Qh;
    const uint32_t* Ql32 = (const uint32_t*)Ql;
    const uint32_t* Kh32 = (const uint32_t*)Kh;
    const uint32_t* Kl32 = (const uint32_t*)Kl;
    const uint32_t* Vh32 = (const uint32_t*)Vh;
    const uint32_t* Vl32 = (const uint32_t*)Vl;

    for (int strip = wid; strip < 14; strip += 8) {
        const int r0 = strip * 16;
        const int ra = r0 + qr, rb = ra + 8;
        int rtA = 591, rtB = 591;
        if (ra < NTOK) { int t = ra / 49, r = ra - t * 49, hh = r / 7, w = r - hh * 7;
                         rtA = t * 169 + hh * 13 + w + 591; }
        if (rb < NTOK) { int t = rb / 49, r = rb - t * 49, hh = r / 7, w = r - hh * 7;
                         rtB = t * 169 + hh * 13 + w + 591; }

        uint32_t qa[2][4], qe[2][4];
        #pragma unroll
        for (int kc = 0; kc < 2; kc++) {
            int b0 = (r0 + qr) * 20 + kc * 8 + qc;
            qa[kc][0] = Qh32[b0];       qa[kc][1] = Qh32[b0 + 160];
            qa[kc][2] = Qh32[b0 + 4];   qa[kc][3] = Qh32[b0 + 164];
            qe[kc][0] = Ql32[b0];       qe[kc][1] = Ql32[b0 + 160];
            qe[kc][2] = Ql32[b0 + 4];   qe[kc][3] = Ql32[b0 + 164];
        }

        float cc[28][4];
        #pragma unroll
        for (int nt = 0; nt < 28; nt++)
            #pragma unroll
            for (int k = 0; k < 4; k++) cc[nt][k] = 0.f;

        #pragma unroll
        for (int nt = 0; nt < 28; nt++) {
            int kb = (nt * 8 + qr) * 20 + qc;
            uint32_t h0 = Kh32[kb], h1 = Kh32[kb + 4], h2 = Kh32[kb + 8], h3 = Kh32[kb + 12];
            uint32_t l0 = Kl32[kb], l1 = Kl32[kb + 4], l2 = Kl32[kb + 8], l3 = Kl32[kb + 12];
            MMA16816(cc[nt], qa[0][0], qa[0][1], qa[0][2], qa[0][3], h0, h1);
            MMA16816(cc[nt], qa[1][0], qa[1][1], qa[1][2], qa[1][3], h2, h3);
            MMA16816(cc[nt], qe[0][0], qe[0][1], qe[0][2], qe[0][3], h0, h1);
            MMA16816(cc[nt], qe[1][0], qe[1][1], qe[1][2], qe[1][3], h2, h3);
            MMA16816(cc[nt], qa[0][0], qa[0][1], qa[0][2], qa[0][3], l0, l1);
            MMA16816(cc[nt], qa[1][0], qa[1][1], qa[1][2], qa[1][3], l2, l3);
        }

        float mA = -1e30f, mB = -1e30f;
        #pragma unroll
        for (int nt = 0; nt < 28; nt++) {
            int c0 = nt * 8 + qc * 2;
            if (c0 < NTOK) {
                int ct = sCT[c0];
                cc[nt][0] += sBias[rtA + ct];
                cc[nt][2] += sBias[rtB + ct];
            } else { cc[nt][0] = -1e30f; cc[nt][2] = -1e30f; }
            if (c0 + 1 < NTOK) {
                int ct = sCT[c0 + 1];
                cc[nt][1] += sBias[rtA + ct];
                cc[nt][3] += sBias[rtB + ct];
            } else { cc[nt][1] = -1e30f; cc[nt][3] = -1e30f; }
            mA = fmaxf(mA, fmaxf(cc[nt][0], cc[nt][1]));
            mB = fmaxf(mB, fmaxf(cc[nt][2], cc[nt][3]));
        }
        mA = fmaxf(mA, __shfl_xor_sync(FULLMASK, mA, 1));
        mA = fmaxf(mA, __shfl_xor_sync(FULLMASK, mA, 2));
        mB = fmaxf(mB, __shfl_xor_sync(FULLMASK, mB, 1));
        mB = fmaxf(mB, __shfl_xor_sync(FULLMASK, mB, 2));

        float sumA = 0.f, sumB = 0.f;
        #pragma unroll
        for (int nt = 0; nt < 28; nt++) {
            cc[nt][0] = __expf(cc[nt][0] - mA); sumA += cc[nt][0];
            cc[nt][1] = __expf(cc[nt][1] - mA); sumA += cc[nt][1];
            cc[nt][2] = __expf(cc[nt][2] - mB); sumB += cc[nt][2];
            cc[nt][3] = __expf(cc[nt][3] - mB); sumB += cc[nt][3];
        }
        sumA += __shfl_xor_sync(FULLMASK, sumA, 1);
        sumA += __shfl_xor_sync(FULLMASK, sumA, 2);
        sumB += __shfl_xor_sync(FULLMASK, sumB, 1);
        sumB += __shfl_xor_sync(FULLMASK, sumB, 2);
        float iA = 1.f / sumA, iB = 1.f / sumB;

        uint32_t ph[14][4], pl[14][4];
        #pragma unroll
        for (int t = 0; t < 14; t++) {
            #pragma unroll
            for (int half = 0; half < 2; half++) {
                float x0 = cc[2 * t][2 * half], x1 = cc[2 * t][2 * half + 1];
                float y0 = cc[2 * t + 1][2 * half], y1 = cc[2 * t + 1][2 * half + 1];
                __nv_bfloat16 hx0 = __float2bfloat16(x0), hx1 = __float2bfloat16(x1);
                __nv_bfloat16 hy0 = __float2bfloat16(y0), hy1 = __float2bfloat16(y1);
                ph[t][half]     = pack_bf2(hx0, hx1);
                ph[t][half + 2] = pack_bf2(hy0, hy1);
                pl[t][half]     = pack_bf2(__float2bfloat16(x0 - __bfloat162float(hx0)),
                                           __float2bfloat16(x1 - __bfloat162float(hx1)));
                pl[t][half + 2] = pack_bf2(__float2bfloat16(y0 - __bfloat162float(hy0)),
                                           __float2bfloat16(y1 - __bfloat162float(hy1)));
            }
        }

        float oo[4][4];
        #pragma unroll
        for (int n2 = 0; n2 < 4; n2++)
            #pragma unroll
            for (int k = 0; k < 4; k++) oo[n2][k] = 0.f;

        #pragma unroll
        for (int t = 0; t < 14; t++) {
            #pragma unroll
            for (int n2 = 0; n2 < 4; n2++) {
                int vb = (t * 8 + qc) * 40 + n2 * 8 + qr;
                uint32_t bh0 = Vh32[vb], bh1 = Vh32[vb + 160];
                uint32_t bl0 = Vl32[vb], bl1 = Vl32[vb + 160];
                MMA16816(oo[n2], ph[t][0], ph[t][1], ph[t][2], ph[t][3], bh0, bh1);
                MMA16816(oo[n2], pl[t][0], pl[t][1], pl[t][2], pl[t][3], bh0, bh1);
                MMA16816(oo[n2], ph[t][0], ph[t][1], ph[t][2], ph[t][3], bl0, bl1);
            }
        }

        if (ra < NTOK) {
            size_t wb = ((size_t)(b_ * NTOK + ra)) * CDIM + h * HD;
            #pragma unroll
            for (int n2 = 0; n2 < 4; n2++) {
                int col = n2 * 8 + qc * 2;
                float x = oo[n2][0] * iA, y = oo[n2][1] * iA;
                ((uint32_t*)g_ath)[(wb + col) >> 1] =
                    pack_h2(__float2half_rn(x), __float2half_rn(y));
            }
        }
        if (rb < NTOK) {
            size_t wb = ((size_t)(b_ * NTOK + rb)) * CDIM + h * HD;
            #pragma unroll
            for (int n2 = 0; n2 < 4; n2++) {
                int col = n2 * 8 + qc * 2;
                float x = oo[n2][2] * iB, y = oo[n2][3] * iB;
                ((uint32_t*)g_ath)[(wb + col) >> 1] =
                    pack_h2(__float2half_rn(x), __float2half_rn(y));
            }
        }
    }
}

// ---------------------------------------------------------------------------
extern "C" void kernel_launch(void* const* d_in, const int* in_sizes, int n_in,
                              void* d_out, int out_size)
{
    const float* x      = (const float*)d_in[0];
    const float* qg     = (const float*)d_in[1];
    const float* kv_w   = (const float*)d_in[2];
    const float* kv_b   = (const float*)d_in[3];
    const float* proj_w = (const float*)d_in[4];
    const float* proj_b = (const float*)d_in[5];
    const float* btab   = (const float*)d_in[6];
    float* out = (float*)d_out;

    cudaFuncSetAttribute(attn_mma, cudaFuncAttributeMaxDynamicSharedMemorySize,
                         ATTN_SMEM_B);
    cudaFuncSetAttribute(gemm_mma<true>, cudaFuncAttributeMaxDynamicSharedMemorySize,
                         GEMM_SMEM);
    cudaFuncSetAttribute(gemm_mma<false>, cudaFuncAttributeMaxDynamicSharedMemorySize,
                         GEMM_SMEM);

    __half *xh, *kwh, *pwh, *ath;
    cudaGetSymbolAddress((void**)&xh,  g_xh);
    cudaGetSymbolAddress((void**)&kwh, g_kwh);
    cudaGetSymbolAddress((void**)&pwh, g_pwh);
    cudaGetSymbolAddress((void**)&ath, g_ath);

    int n4x = XELT / 4;
    round16_kernel<<<(n4x + 255) / 256, 256>>>(x, xh, n4x);
    int n4k = 2 * CDIM * CDIM / 4;
    round16_kernel<<<(n4k + 255) / 256, 256>>>(kv_w, kwh, n4k);
    int n4p = CDIM * CDIM / 4;
    round16_kernel<<<(n4p + 255) / 256, 256>>>(proj_w, pwh, n4p);

    dim3 gkv(2 * CDIM / 128, MROWS / 128);    // (8, 392)
    gemm_mma<true><<<gkv, 256, GEMM_SMEM>>>(xh, kwh, kv_b, nullptr);

    dim3 gat(NHEAD, NWIN);                    // (16, 256)
    attn_mma<<<gat, 256, ATTN_SMEM_B>>>(qg, btab);

    dim3 gpj(CDIM / 128, MROWS / 128);        // (4, 392)
    gemm_mma<false><<<gpj, 256, GEMM_SMEM>>>(ath, pwh, proj_b, out);
}